// round 4
// baseline (speedup 1.0000x reference)
#include <cuda_runtime.h>
#include <cuda_bf16.h>
#include <math.h>
#include <stdint.h>

// Problem constants
#define L_LAYERS 6
#define BATCH    4
#define SEQ      1024
#define HID      768
#define NHEAD    12
#define HDIM     64
#define FFDIM    3072
#define MTOK     (BATCH*SEQ)      // 4096 tokens

// ---------------------------------------------------------------------------
// Scratch (device globals; no allocation allowed in kernel_launch)
// ---------------------------------------------------------------------------
__device__ float g_x   [MTOK*HID];            // hidden state between layers
__device__ float g_q   [MTOK*HID];
__device__ float g_k   [MTOK*HID];
__device__ float g_v   [MTOK*HID];
__device__ float g_sc  [BATCH*NHEAD*SEQ*SEQ]; // attention scores/probs (192 MB)
__device__ float g_ctx [MTOK*HID];
__device__ float g_y   [MTOK*HID];            // pre-LN1
__device__ float g_attn[MTOK*HID];            // LN1 output
__device__ float g_ffh [MTOK*FFDIM];          // FF intermediate
__device__ float g_y2  [MTOK*HID];            // pre-LN2

// bf16 split activations
__device__ __nv_bfloat16 g_xh[MTOK*HID],  g_xl[MTOK*HID];    // layer input
__device__ __nv_bfloat16 g_ch[MTOK*HID],  g_cl[MTOK*HID];    // ctx
__device__ __nv_bfloat16 g_ah[MTOK*HID],  g_al[MTOK*HID];    // LN1 out
__device__ __nv_bfloat16 g_fh[MTOK*FFDIM],g_fl[MTOK*FFDIM];  // FF hidden

// bf16 split weights, stored TRANSPOSED [N,K] so mma B-fragments are contiguous
__device__ __nv_bfloat16 g_qwh[HID*HID],   g_qwl[HID*HID];
__device__ __nv_bfloat16 g_kwh[HID*HID],   g_kwl[HID*HID];
__device__ __nv_bfloat16 g_vwh[HID*HID],   g_vwl[HID*HID];
__device__ __nv_bfloat16 g_awh[HID*HID],   g_awl[HID*HID];
__device__ __nv_bfloat16 g_f1h[HID*FFDIM], g_f1l[HID*FFDIM];
__device__ __nv_bfloat16 g_f2h[FFDIM*HID], g_f2l[FFDIM*HID];

// ---------------------------------------------------------------------------
// Split helpers
// ---------------------------------------------------------------------------
__global__ __launch_bounds__(256)
void split_act(const float* __restrict__ x, __nv_bfloat16* __restrict__ h,
               __nv_bfloat16* __restrict__ l, int n)
{
    int i = (blockIdx.x * 256 + threadIdx.x) * 4;
    if (i >= n) return;
    float4 v = *reinterpret_cast<const float4*>(x + i);
    __nv_bfloat16 h0 = __float2bfloat16_rn(v.x);
    __nv_bfloat16 h1 = __float2bfloat16_rn(v.y);
    __nv_bfloat16 h2 = __float2bfloat16_rn(v.z);
    __nv_bfloat16 h3 = __float2bfloat16_rn(v.w);
    __nv_bfloat16 l0 = __float2bfloat16_rn(v.x - __bfloat162float(h0));
    __nv_bfloat16 l1 = __float2bfloat16_rn(v.y - __bfloat162float(h1));
    __nv_bfloat16 l2 = __float2bfloat16_rn(v.z - __bfloat162float(h2));
    __nv_bfloat16 l3 = __float2bfloat16_rn(v.w - __bfloat162float(h3));
    __nv_bfloat162* hp = reinterpret_cast<__nv_bfloat162*>(h + i);
    __nv_bfloat162* lp = reinterpret_cast<__nv_bfloat162*>(l + i);
    hp[0] = __nv_bfloat162(h0, h1); hp[1] = __nv_bfloat162(h2, h3);
    lp[0] = __nv_bfloat162(l0, l1); lp[1] = __nv_bfloat162(l2, l3);
}

// W[K,N] row-major -> split, transposed to [N,K]
__global__ __launch_bounds__(256)
void split_wT(const float* __restrict__ W, __nv_bfloat16* __restrict__ hT,
              __nv_bfloat16* __restrict__ lT, int K, int N)
{
    int idx = blockIdx.x * 256 + threadIdx.x;
    if (idx >= K * N) return;
    int k = idx / N, n = idx - k * N;
    float v = W[idx];
    __nv_bfloat16 h = __float2bfloat16_rn(v);
    __nv_bfloat16 l = __float2bfloat16_rn(v - __bfloat162float(h));
    hT[(size_t)n * K + k] = h;
    lT[(size_t)n * K + k] = l;
}

// ---------------------------------------------------------------------------
// Tensor-core GEMM (3-term bf16 split, fp32 accumulate):
//   C[M,N] = A @ W + bias (+res) (+GELU),  A:[M,K] (Ah,Al), W as (WhT,WlT):[N,K]
// BM=BN=128, BK=16; 256 threads = 8 warps (2x4), warp tile 64x32.
// Smem: 4 tiles x 2 stages x [128][24] bf16 = 48KB. One barrier per k-step.
// ---------------------------------------------------------------------------
__device__ __forceinline__ void mma16816(float* c, const uint32_t* a, const uint32_t* b)
{
    asm("mma.sync.aligned.m16n8k16.row.col.f32.bf16.bf16.f32 "
        "{%0,%1,%2,%3}, {%4,%5,%6,%7}, {%8,%9}, {%0,%1,%2,%3};"
        : "+f"(c[0]), "+f"(c[1]), "+f"(c[2]), "+f"(c[3])
        : "r"(a[0]), "r"(a[1]), "r"(a[2]), "r"(a[3]), "r"(b[0]), "r"(b[1]));
}

template<int ACT, bool HASRES>
__global__ __launch_bounds__(256, 1)
void tc_gemm(const __nv_bfloat16* __restrict__ Ah, const __nv_bfloat16* __restrict__ Al,
             const __nv_bfloat16* __restrict__ WhT, const __nv_bfloat16* __restrict__ WlT,
             const float* __restrict__ bias, const float* __restrict__ res,
             float* __restrict__ C, int Mdim, int Ndim, int Kdim)
{
    __shared__ __nv_bfloat16 sAh[2][128][24];
    __shared__ __nv_bfloat16 sAl[2][128][24];
    __shared__ __nv_bfloat16 sBh[2][128][24];
    __shared__ __nv_bfloat16 sBl[2][128][24];

    const int tid  = threadIdx.x;
    const int row0 = blockIdx.y * 128;   // M offset
    const int col0 = blockIdx.x * 128;   // N offset

    // global->smem mapping: each thread loads 8 bf16 (16B) per tile
    const int lrow = tid >> 1;           // 0..127
    const int kofs = (tid & 1) * 8;      // 0 or 8

    const __nv_bfloat16* pAh = Ah  + (size_t)(row0 + lrow) * Kdim + kofs;
    const __nv_bfloat16* pAl = Al  + (size_t)(row0 + lrow) * Kdim + kofs;
    const __nv_bfloat16* pBh = WhT + (size_t)(col0 + lrow) * Kdim + kofs;
    const __nv_bfloat16* pBl = WlT + (size_t)(col0 + lrow) * Kdim + kofs;

    // warp/fragment indexing
    const int wid  = tid >> 5;
    const int wr   = wid & 1;            // 0..1 -> m
    const int wc   = wid >> 1;           // 0..3 -> n
    const int m0   = wr * 64;
    const int n0   = wc * 32;
    const int lane = tid & 31;
    const int gg   = lane >> 2;          // 0..7
    const int tg   = lane & 3;           // 0..3

    float acc[4][4][4];
#pragma unroll
    for (int i = 0; i < 4; i++)
#pragma unroll
        for (int j = 0; j < 4; j++)
#pragma unroll
            for (int t = 0; t < 4; t++) acc[i][j][t] = 0.f;

    // preload stage 0
    {
        uint4 a_h = *reinterpret_cast<const uint4*>(pAh);
        uint4 a_l = *reinterpret_cast<const uint4*>(pAl);
        uint4 b_h = *reinterpret_cast<const uint4*>(pBh);
        uint4 b_l = *reinterpret_cast<const uint4*>(pBl);
        *reinterpret_cast<uint4*>(&sAh[0][lrow][kofs]) = a_h;
        *reinterpret_cast<uint4*>(&sAl[0][lrow][kofs]) = a_l;
        *reinterpret_cast<uint4*>(&sBh[0][lrow][kofs]) = b_h;
        *reinterpret_cast<uint4*>(&sBl[0][lrow][kofs]) = b_l;
    }
    __syncthreads();

    int s = 0;
    for (int k0 = 0; k0 < Kdim; k0 += 16) {
        const bool has_next = (k0 + 16 < Kdim);
        uint4 nAh, nAl, nBh, nBl;
        if (has_next) {
            nAh = *reinterpret_cast<const uint4*>(pAh + k0 + 16);
            nAl = *reinterpret_cast<const uint4*>(pAl + k0 + 16);
            nBh = *reinterpret_cast<const uint4*>(pBh + k0 + 16);
            nBl = *reinterpret_cast<const uint4*>(pBl + k0 + 16);
        }

        // load fragments
        uint32_t afh[4][4], afl[4][4], bfh[4][2], bfl[4][2];
#pragma unroll
        for (int i = 0; i < 4; i++) {
            const int r = m0 + i * 16;
            afh[i][0] = *reinterpret_cast<const uint32_t*>(&sAh[s][r + gg    ][2 * tg    ]);
            afh[i][1] = *reinterpret_cast<const uint32_t*>(&sAh[s][r + 8 + gg][2 * tg    ]);
            afh[i][2] = *reinterpret_cast<const uint32_t*>(&sAh[s][r + gg    ][2 * tg + 8]);
            afh[i][3] = *reinterpret_cast<const uint32_t*>(&sAh[s][r + 8 + gg][2 * tg + 8]);
            afl[i][0] = *reinterpret_cast<const uint32_t*>(&sAl[s][r + gg    ][2 * tg    ]);
            afl[i][1] = *reinterpret_cast<const uint32_t*>(&sAl[s][r + 8 + gg][2 * tg    ]);
            afl[i][2] = *reinterpret_cast<const uint32_t*>(&sAl[s][r + gg    ][2 * tg + 8]);
            afl[i][3] = *reinterpret_cast<const uint32_t*>(&sAl[s][r + 8 + gg][2 * tg + 8]);
        }
#pragma unroll
        for (int j = 0; j < 4; j++) {
            const int c = n0 + j * 8;
            bfh[j][0] = *reinterpret_cast<const uint32_t*>(&sBh[s][c + gg][2 * tg    ]);
            bfh[j][1] = *reinterpret_cast<const uint32_t*>(&sBh[s][c + gg][2 * tg + 8]);
            bfl[j][0] = *reinterpret_cast<const uint32_t*>(&sBl[s][c + gg][2 * tg    ]);
            bfl[j][1] = *reinterpret_cast<const uint32_t*>(&sBl[s][c + gg][2 * tg + 8]);
        }

#pragma unroll
        for (int i = 0; i < 4; i++)
#pragma unroll
            for (int j = 0; j < 4; j++) {
                mma16816(acc[i][j], afh[i], bfh[j]);   // Ah*Wh
                mma16816(acc[i][j], afh[i], bfl[j]);   // Ah*Wl
                mma16816(acc[i][j], afl[i], bfh[j]);   // Al*Wh
            }

        if (has_next) {
            const int ns = s ^ 1;
            *reinterpret_cast<uint4*>(&sAh[ns][lrow][kofs]) = nAh;
            *reinterpret_cast<uint4*>(&sAl[ns][lrow][kofs]) = nAl;
            *reinterpret_cast<uint4*>(&sBh[ns][lrow][kofs]) = nBh;
            *reinterpret_cast<uint4*>(&sBl[ns][lrow][kofs]) = nBl;
            __syncthreads();
        }
        s ^= 1;
    }

    // epilogue: each (i,j) frag holds rows {gg, gg+8}, cols {2tg, 2tg+1}
#pragma unroll
    for (int i = 0; i < 4; i++) {
        const int r_lo = row0 + m0 + i * 16 + gg;
        const int r_hi = r_lo + 8;
#pragma unroll
        for (int j = 0; j < 4; j++) {
            const int c = col0 + n0 + j * 8 + 2 * tg;
            float2 b2 = *reinterpret_cast<const float2*>(bias + c);
            float v0 = acc[i][j][0] + b2.x;
            float v1 = acc[i][j][1] + b2.y;
            float v2 = acc[i][j][2] + b2.x;
            float v3 = acc[i][j][3] + b2.y;
            if (HASRES) {
                float2 r0 = *reinterpret_cast<const float2*>(res + (size_t)r_lo * Ndim + c);
                float2 r1 = *reinterpret_cast<const float2*>(res + (size_t)r_hi * Ndim + c);
                v0 += r0.x; v1 += r0.y; v2 += r1.x; v3 += r1.y;
            }
            if (ACT == 1) {
                v0 = 0.5f * v0 * (1.f + erff(v0 * 0.7071067811865475f));
                v1 = 0.5f * v1 * (1.f + erff(v1 * 0.7071067811865475f));
                v2 = 0.5f * v2 * (1.f + erff(v2 * 0.7071067811865475f));
                v3 = 0.5f * v3 * (1.f + erff(v3 * 0.7071067811865475f));
            }
            *reinterpret_cast<float2*>(C + (size_t)r_lo * Ndim + c) = make_float2(v0, v1);
            *reinterpret_cast<float2*>(C + (size_t)r_hi * Ndim + c) = make_float2(v2, v3);
        }
    }
}

// ---------------------------------------------------------------------------
// Attention scores:  S[b,h,q,k] = (Q_bh[q,:] . K_bh[k,:]) / 8 + mask[b,k]
// fp32 NT GEMM, 128x128 tiles, BK=8, double-buffered smem.
// ---------------------------------------------------------------------------
__global__ __launch_bounds__(256)
void attn_scores(const float* __restrict__ q, const float* __restrict__ kmat,
                 const float* __restrict__ mask, float* __restrict__ sc)
{
    const int z = blockIdx.z;
    const int b = z / NHEAD, h = z % NHEAD;
    const float* Qb = q    + (size_t)b * SEQ * HID + h * HDIM;
    const float* Kb = kmat + (size_t)b * SEQ * HID + h * HDIM;
    float*       Cb = sc   + (size_t)z * SEQ * SEQ;
    const float* mb = mask + (size_t)b * SEQ;

    __shared__ float As[2][8][128];
    __shared__ float Bs[2][8][128];

    const int tid  = threadIdx.x;
    const int tx   = tid & 15, ty = tid >> 4;
    const int row0 = blockIdx.y * 128;
    const int col0 = blockIdx.x * 128;
    const int lr   = tid >> 1;
    const int lc4  = (tid & 1) * 4;

    const float* Qp = Qb + (size_t)(row0 + lr) * HID + lc4;
    const float* Kp = Kb + (size_t)(col0 + lr) * HID + lc4;

    float acc[8][8];
#pragma unroll
    for (int i = 0; i < 8; i++)
#pragma unroll
        for (int j = 0; j < 8; j++) acc[i][j] = 0.f;

    {
        float4 a4 = *reinterpret_cast<const float4*>(Qp);
        float4 b4 = *reinterpret_cast<const float4*>(Kp);
        As[0][lc4 + 0][lr] = a4.x; As[0][lc4 + 1][lr] = a4.y;
        As[0][lc4 + 2][lr] = a4.z; As[0][lc4 + 3][lr] = a4.w;
        Bs[0][lc4 + 0][lr] = b4.x; Bs[0][lc4 + 1][lr] = b4.y;
        Bs[0][lc4 + 2][lr] = b4.z; Bs[0][lc4 + 3][lr] = b4.w;
    }
    __syncthreads();

    int buf = 0;
    for (int k0 = 0; k0 < HDIM; k0 += 8) {
        const bool has_next = (k0 + 8 < HDIM);
        float4 na, nb4;
        if (has_next) {
            na  = *reinterpret_cast<const float4*>(Qp + k0 + 8);
            nb4 = *reinterpret_cast<const float4*>(Kp + k0 + 8);
        }

#pragma unroll
        for (int kk = 0; kk < 8; kk++) {
            float a[8], b[8];
            *reinterpret_cast<float4*>(a)     = *reinterpret_cast<const float4*>(&As[buf][kk][ty * 8]);
            *reinterpret_cast<float4*>(a + 4) = *reinterpret_cast<const float4*>(&As[buf][kk][ty * 8 + 4]);
            *reinterpret_cast<float4*>(b)     = *reinterpret_cast<const float4*>(&Bs[buf][kk][tx * 8]);
            *reinterpret_cast<float4*>(b + 4) = *reinterpret_cast<const float4*>(&Bs[buf][kk][tx * 8 + 4]);
#pragma unroll
            for (int i = 0; i < 8; i++)
#pragma unroll
                for (int j = 0; j < 8; j++) acc[i][j] += a[i] * b[j];
        }

        if (has_next) {
            const int nbuf = buf ^ 1;
            As[nbuf][lc4 + 0][lr] = na.x;  As[nbuf][lc4 + 1][lr] = na.y;
            As[nbuf][lc4 + 2][lr] = na.z;  As[nbuf][lc4 + 3][lr] = na.w;
            Bs[nbuf][lc4 + 0][lr] = nb4.x; Bs[nbuf][lc4 + 1][lr] = nb4.y;
            Bs[nbuf][lc4 + 2][lr] = nb4.z; Bs[nbuf][lc4 + 3][lr] = nb4.w;
            __syncthreads();
        }
        buf ^= 1;
    }

    const int cbase = col0 + tx * 8;
    float4 m_lo = *reinterpret_cast<const float4*>(mb + cbase);
    float4 m_hi = *reinterpret_cast<const float4*>(mb + cbase + 4);

#pragma unroll
    for (int i = 0; i < 8; i++) {
        const int r = row0 + ty * 8 + i;
        float4 lo, hi;
        lo.x = acc[i][0] * 0.125f + m_lo.x; lo.y = acc[i][1] * 0.125f + m_lo.y;
        lo.z = acc[i][2] * 0.125f + m_lo.z; lo.w = acc[i][3] * 0.125f + m_lo.w;
        hi.x = acc[i][4] * 0.125f + m_hi.x; hi.y = acc[i][5] * 0.125f + m_hi.y;
        hi.z = acc[i][6] * 0.125f + m_hi.z; hi.w = acc[i][7] * 0.125f + m_hi.w;
        *reinterpret_cast<float4*>(Cb + (size_t)r * SEQ + cbase)     = lo;
        *reinterpret_cast<float4*>(Cb + (size_t)r * SEQ + cbase + 4) = hi;
    }
}

// ---------------------------------------------------------------------------
// Row softmax over 1024 keys. One block (256 thr) per row, in place.
// ---------------------------------------------------------------------------
__global__ __launch_bounds__(256)
void softmax_rows(float* __restrict__ sc)
{
    float* p = sc + (size_t)blockIdx.x * SEQ;
    const int tid = threadIdx.x;
    __shared__ float red[8];

    float4 v = *reinterpret_cast<const float4*>(p + tid * 4);
    float mx = fmaxf(fmaxf(v.x, v.y), fmaxf(v.z, v.w));
#pragma unroll
    for (int o = 16; o; o >>= 1) mx = fmaxf(mx, __shfl_xor_sync(0xffffffffu, mx, o));
    if ((tid & 31) == 0) red[tid >> 5] = mx;
    __syncthreads();
    float m = red[0];
#pragma unroll
    for (int i = 1; i < 8; i++) m = fmaxf(m, red[i]);
    __syncthreads();

    v.x = expf(v.x - m); v.y = expf(v.y - m);
    v.z = expf(v.z - m); v.w = expf(v.w - m);
    float s = v.x + v.y + v.z + v.w;
#pragma unroll
    for (int o = 16; o; o >>= 1) s += __shfl_xor_sync(0xffffffffu, s, o);
    if ((tid & 31) == 0) red[tid >> 5] = s;
    __syncthreads();
    float tot = 0.f;
#pragma unroll
    for (int i = 0; i < 8; i++) tot += red[i];
    const float inv = 1.f / tot;
    v.x *= inv; v.y *= inv; v.z *= inv; v.w *= inv;
    *reinterpret_cast<float4*>(p + tid * 4) = v;
}

// ---------------------------------------------------------------------------
// ctx = P @ V per (b,h): M=SEQ, N=HDIM(64), K=SEQ. fp32, double-buffered.
// ---------------------------------------------------------------------------
__global__ __launch_bounds__(256)
void attn_pv(const float* __restrict__ sc, const float* __restrict__ v,
             float* __restrict__ ctx)
{
    const int z = blockIdx.y;
    const int b = z / NHEAD, h = z % NHEAD;
    const float* Pb = sc + (size_t)z * SEQ * SEQ;
    const float* Vb = v  + (size_t)b * SEQ * HID + h * HDIM;

    __shared__ float As[2][8][128];
    __shared__ float Bs[2][8][64];

    const int tid  = threadIdx.x;
    const int tx   = tid & 15, ty = tid >> 4;
    const int row0 = blockIdx.x * 128;
    const int lr   = tid >> 1;
    const int lc4  = (tid & 1) * 4;
    const int brow = tid >> 5;          // 0..7
    const int bc2  = (tid & 31) * 2;    // 0..62

    const float* Pp = Pb + (size_t)(row0 + lr) * SEQ + lc4;
    const float* Vp = Vb + (size_t)brow * HID + bc2;

    float acc[8][4];
#pragma unroll
    for (int i = 0; i < 8; i++)
#pragma unroll
        for (int j = 0; j < 4; j++) acc[i][j] = 0.f;

    {
        float4 a4 = *reinterpret_cast<const float4*>(Pp);
        float2 b2 = *reinterpret_cast<const float2*>(Vp);
        As[0][lc4 + 0][lr] = a4.x; As[0][lc4 + 1][lr] = a4.y;
        As[0][lc4 + 2][lr] = a4.z; As[0][lc4 + 3][lr] = a4.w;
        Bs[0][brow][bc2] = b2.x;   Bs[0][brow][bc2 + 1] = b2.y;
    }
    __syncthreads();

    int buf = 0;
    for (int k0 = 0; k0 < SEQ; k0 += 8) {
        const bool has_next = (k0 + 8 < SEQ);
        float4 na;
        float2 nb2;
        if (has_next) {
            na  = *reinterpret_cast<const float4*>(Pp + k0 + 8);
            nb2 = *reinterpret_cast<const float2*>(Vp + (size_t)(k0 + 8) * HID);
        }

#pragma unroll
        for (int kk = 0; kk < 8; kk++) {
            float a[8], bb[4];
            *reinterpret_cast<float4*>(a)     = *reinterpret_cast<const float4*>(&As[buf][kk][ty * 8]);
            *reinterpret_cast<float4*>(a + 4) = *reinterpret_cast<const float4*>(&As[buf][kk][ty * 8 + 4]);
            *reinterpret_cast<float4*>(bb)    = *reinterpret_cast<const float4*>(&Bs[buf][kk][tx * 4]);
#pragma unroll
            for (int i = 0; i < 8; i++)
#pragma unroll
                for (int j = 0; j < 4; j++) acc[i][j] += a[i] * bb[j];
        }

        if (has_next) {
            const int nb = buf ^ 1;
            As[nb][lc4 + 0][lr] = na.x; As[nb][lc4 + 1][lr] = na.y;
            As[nb][lc4 + 2][lr] = na.z; As[nb][lc4 + 3][lr] = na.w;
            Bs[nb][brow][bc2] = nb2.x;  Bs[nb][brow][bc2 + 1] = nb2.y;
            __syncthreads();
        }
        buf ^= 1;
    }

#pragma unroll
    for (int i = 0; i < 8; i++) {
        const int r = row0 + ty * 8 + i;
        float4 o;
        o.x = acc[i][0]; o.y = acc[i][1]; o.z = acc[i][2]; o.w = acc[i][3];
        *reinterpret_cast<float4*>(ctx + (size_t)(b * SEQ + r) * HID + h * HDIM + tx * 4) = o;
    }
}

// ---------------------------------------------------------------------------
// LayerNorm over last dim (768). One block (256 thr, 3 elems each) per row.
// ---------------------------------------------------------------------------
__global__ __launch_bounds__(256)
void layernorm(const float* __restrict__ x, const float* __restrict__ gam,
               const float* __restrict__ bet, float* __restrict__ out)
{
    const int row = blockIdx.x;
    const float* xr = x + (size_t)row * HID;
    const int tid = threadIdx.x;
    __shared__ float rs_[8], rq_[8];

    float v0 = xr[tid], v1 = xr[tid + 256], v2 = xr[tid + 512];
    float s  = v0 + v1 + v2;
    float sq = v0 * v0 + v1 * v1 + v2 * v2;
#pragma unroll
    for (int o = 16; o; o >>= 1) {
        s  += __shfl_xor_sync(0xffffffffu, s,  o);
        sq += __shfl_xor_sync(0xffffffffu, sq, o);
    }
    if ((tid & 31) == 0) { rs_[tid >> 5] = s; rq_[tid >> 5] = sq; }
    __syncthreads();
    float ts = 0.f, tq = 0.f;
#pragma unroll
    for (int i = 0; i < 8; i++) { ts += rs_[i]; tq += rq_[i]; }
    const float mean = ts * (1.f / HID);
    const float var  = tq * (1.f / HID) - mean * mean;
    const float rstd = rsqrtf(var + 1e-5f);

    float* o = out + (size_t)row * HID;
    o[tid]       = (v0 - mean) * rstd * gam[tid]       + bet[tid];
    o[tid + 256] = (v1 - mean) * rstd * gam[tid + 256] + bet[tid + 256];
    o[tid + 512] = (v2 - mean) * rstd * gam[tid + 512] + bet[tid + 512];
}

// ---------------------------------------------------------------------------
// Launcher (graph-capturable: kernel launches only)
// ---------------------------------------------------------------------------
extern "C" void kernel_launch(void* const* d_in, const int* in_sizes, int n_in,
                              void* d_out, int out_size)
{
    (void)in_sizes; (void)n_in; (void)out_size;
    const float* hs    = (const float*)d_in[0];
    const float* mask  = (const float*)d_in[1];
    const float* q_w   = (const float*)d_in[2];
    const float* q_b   = (const float*)d_in[3];
    const float* k_w   = (const float*)d_in[4];
    const float* k_b   = (const float*)d_in[5];
    const float* v_w   = (const float*)d_in[6];
    const float* v_b   = (const float*)d_in[7];
    const float* ao_w  = (const float*)d_in[8];
    const float* ao_b  = (const float*)d_in[9];
    const float* ln1_g = (const float*)d_in[10];
    const float* ln1_b = (const float*)d_in[11];
    const float* ff1_w = (const float*)d_in[12];
    const float* ff1_b = (const float*)d_in[13];
    const float* ff2_w = (const float*)d_in[14];
    const float* ff2_b = (const float*)d_in[15];
    const float* ln2_g = (const float*)d_in[16];
    const float* ln2_b = (const float*)d_in[17];
    float* out = (float*)d_out;

    float *x, *q, *k, *v, *sc, *ctx, *y, *attn, *ffh, *y2;
    cudaGetSymbolAddress((void**)&x,    g_x);
    cudaGetSymbolAddress((void**)&q,    g_q);
    cudaGetSymbolAddress((void**)&k,    g_k);
    cudaGetSymbolAddress((void**)&v,    g_v);
    cudaGetSymbolAddress((void**)&sc,   g_sc);
    cudaGetSymbolAddress((void**)&ctx,  g_ctx);
    cudaGetSymbolAddress((void**)&y,    g_y);
    cudaGetSymbolAddress((void**)&attn, g_attn);
    cudaGetSymbolAddress((void**)&ffh,  g_ffh);
    cudaGetSymbolAddress((void**)&y2,   g_y2);

    __nv_bfloat16 *xh, *xl, *ch, *cl, *ah, *al, *fh, *fl;
    cudaGetSymbolAddress((void**)&xh, g_xh); cudaGetSymbolAddress((void**)&xl, g_xl);
    cudaGetSymbolAddress((void**)&ch, g_ch); cudaGetSymbolAddress((void**)&cl, g_cl);
    cudaGetSymbolAddress((void**)&ah, g_ah); cudaGetSymbolAddress((void**)&al, g_al);
    cudaGetSymbolAddress((void**)&fh, g_fh); cudaGetSymbolAddress((void**)&fl, g_fl);

    __nv_bfloat16 *qwh, *qwl, *kwh, *kwl, *vwh, *vwl, *awh, *awl, *f1h, *f1l, *f2h, *f2l;
    cudaGetSymbolAddress((void**)&qwh, g_qwh); cudaGetSymbolAddress((void**)&qwl, g_qwl);
    cudaGetSymbolAddress((void**)&kwh, g_kwh); cudaGetSymbolAddress((void**)&kwl, g_kwl);
    cudaGetSymbolAddress((void**)&vwh, g_vwh); cudaGetSymbolAddress((void**)&vwl, g_vwl);
    cudaGetSymbolAddress((void**)&awh, g_awh); cudaGetSymbolAddress((void**)&awl, g_awl);
    cudaGetSymbolAddress((void**)&f1h, g_f1h); cudaGetSymbolAddress((void**)&f1l, g_f1l);
    cudaGetSymbolAddress((void**)&f2h, g_f2h); cudaGetSymbolAddress((void**)&f2l, g_f2l);

    // ---- weight split+transpose (deterministic, idempotent) ----
    const int nHH = HID * HID, nHF = HID * FFDIM;
    split_wT<<<(nHH + 255) / 256, 256>>>(q_w,  qwh, qwl, HID, HID);
    split_wT<<<(nHH + 255) / 256, 256>>>(k_w,  kwh, kwl, HID, HID);
    split_wT<<<(nHH + 255) / 256, 256>>>(v_w,  vwh, vwl, HID, HID);
    split_wT<<<(nHH + 255) / 256, 256>>>(ao_w, awh, awl, HID, HID);
    split_wT<<<(nHF + 255) / 256, 256>>>(ff1_w, f1h, f1l, HID, FFDIM);
    split_wT<<<(nHF + 255) / 256, 256>>>(ff2_w, f2h, f2l, FFDIM, HID);

    const dim3 gH (HID   / 128, MTOK / 128);   // (6, 32)
    const dim3 gFF(FFDIM / 128, MTOK / 128);   // (24, 32)
    const dim3 gSc(SEQ / 128, SEQ / 128, BATCH * NHEAD);
    const dim3 gPV(SEQ / 128, BATCH * NHEAD);
    const int nACT  = MTOK * HID;
    const int nACTF = MTOK * FFDIM;

    for (int l = 0; l < L_LAYERS; l++) {
        const float* xin = (l == 0) ? hs : x;

        split_act<<<(nACT / 4 + 255) / 256, 256>>>(xin, xh, xl, nACT);

        tc_gemm<0, false><<<gH, 256>>>(xh, xl, qwh, qwl, q_b, nullptr, q, MTOK, HID, HID);
        tc_gemm<0, false><<<gH, 256>>>(xh, xl, kwh, kwl, k_b, nullptr, k, MTOK, HID, HID);
        tc_gemm<0, false><<<gH, 256>>>(xh, xl, vwh, vwl, v_b, nullptr, v, MTOK, HID, HID);

        attn_scores<<<gSc, 256>>>(q, k, mask, sc);
        softmax_rows<<<BATCH * NHEAD * SEQ, 256>>>(sc);
        attn_pv<<<gPV, 256>>>(sc, v, ctx);

        split_act<<<(nACT / 4 + 255) / 256, 256>>>(ctx, ch, cl, nACT);
        tc_gemm<0, true><<<gH, 256>>>(ch, cl, awh, awl, ao_b, xin, y, MTOK, HID, HID);
        layernorm<<<MTOK, 256>>>(y, ln1_g, ln1_b, attn);

        split_act<<<(nACT / 4 + 255) / 256, 256>>>(attn, ah, al, nACT);
        tc_gemm<1, false><<<gFF, 256>>>(ah, al, f1h, f1l, ff1_b, nullptr, ffh, MTOK, FFDIM, HID);

        split_act<<<(nACTF / 4 + 255) / 256, 256>>>(ffh, fh, fl, nACTF);
        tc_gemm<0, true><<<gH, 256>>>(fh, fl, f2h, f2l, ff2_b, attn, y2, MTOK, HID, FFDIM);

        float* xo = (l == L_LAYERS - 1) ? out : x;
        layernorm<<<MTOK, 256>>>(y2, ln2_g, ln2_b, xo);
    }
}

// round 8
// speedup vs baseline: 1.0863x; 1.0863x over previous
#include <cuda_runtime.h>
#include <cuda_bf16.h>
#include <math.h>
#include <stdint.h>

#define L_LAYERS 6
#define BATCH    4
#define SEQ      1024
#define HID      768
#define NHEAD    12
#define HDIM     64
#define FFDIM    3072
#define MTOK     (BATCH*SEQ)      // 4096 tokens
#define NBH      (BATCH*NHEAD)    // 48

typedef __nv_bfloat16 bf16;

// ---------------------------------------------------------------------------
// Scratch (device globals)
// ---------------------------------------------------------------------------
__device__ float g_x   [MTOK*HID];
__device__ float g_v   [MTOK*HID];
__device__ float g_sc  [NBH*SEQ*SEQ];        // fp32 logits (192 MB)
__device__ float g_y   [MTOK*HID];
__device__ float g_attn[MTOK*HID];
__device__ float g_y2  [MTOK*HID];

__device__ bf16 g_xh[MTOK*HID],  g_xl[MTOK*HID];
__device__ bf16 g_qh[MTOK*HID],  g_ql[MTOK*HID];
__device__ bf16 g_kh[MTOK*HID],  g_kl[MTOK*HID];
__device__ bf16 g_vth[MTOK*HID], g_vtl[MTOK*HID];   // V^T per batch [HID][SEQ]
__device__ bf16 g_ch[MTOK*HID],  g_cl[MTOK*HID];    // ctx split
__device__ bf16 g_ah[MTOK*HID],  g_al[MTOK*HID];    // LN1 split
__device__ bf16 g_fh[MTOK*FFDIM],g_fl[MTOK*FFDIM];  // FF hidden split
__device__ bf16 g_ph[NBH*SEQ*SEQ], g_pl[NBH*SEQ*SEQ]; // probs split (96MB x2)

// weights split, transposed [N,K]
__device__ bf16 g_qwh[HID*HID],   g_qwl[HID*HID];
__device__ bf16 g_kwh[HID*HID],   g_kwl[HID*HID];
__device__ bf16 g_vwh[HID*HID],   g_vwl[HID*HID];
__device__ bf16 g_awh[HID*HID],   g_awl[HID*HID];
__device__ bf16 g_f1h[HID*FFDIM], g_f1l[HID*FFDIM];
__device__ bf16 g_f2h[FFDIM*HID], g_f2l[FFDIM*HID];

__device__ __forceinline__ void split2(float v, bf16& h, bf16& l)
{
    h = __float2bfloat16_rn(v);
    l = __float2bfloat16_rn(v - __bfloat162float(h));
}

// ---------------------------------------------------------------------------
// Split helpers
// ---------------------------------------------------------------------------
__global__ __launch_bounds__(256)
void split_act(const float* __restrict__ x, bf16* __restrict__ h,
               bf16* __restrict__ l, int n)
{
    int i = (blockIdx.x * 256 + threadIdx.x) * 4;
    if (i >= n) return;
    float4 v = *reinterpret_cast<const float4*>(x + i);
    bf16 h0, h1, h2, h3, l0, l1, l2, l3;
    split2(v.x, h0, l0); split2(v.y, h1, l1);
    split2(v.z, h2, l2); split2(v.w, h3, l3);
    __nv_bfloat162* hp = reinterpret_cast<__nv_bfloat162*>(h + i);
    __nv_bfloat162* lp = reinterpret_cast<__nv_bfloat162*>(l + i);
    hp[0] = __nv_bfloat162(h0, h1); hp[1] = __nv_bfloat162(h2, h3);
    lp[0] = __nv_bfloat162(l0, l1); lp[1] = __nv_bfloat162(l2, l3);
}

// W[K,N] row-major -> split, transposed to [N,K]
__global__ __launch_bounds__(256)
void split_wT(const float* __restrict__ W, bf16* __restrict__ hT,
              bf16* __restrict__ lT, int K, int N)
{
    int idx = blockIdx.x * 256 + threadIdx.x;
    if (idx >= K * N) return;
    int k = idx / N, n = idx - k * N;
    bf16 h, l;
    split2(W[idx], h, l);
    hT[(size_t)n * K + k] = h;
    lT[(size_t)n * K + k] = l;
}

// V [B,S,HID] fp32 -> per-batch transposed split [B][HID][SEQ]
__global__ __launch_bounds__(256)
void split_vT(const float* __restrict__ v, bf16* __restrict__ th,
              bf16* __restrict__ tl)
{
    __shared__ float tile[32][33];
    const int b  = blockIdx.z;
    const int s0 = blockIdx.x * 32;
    const int d0 = blockIdx.y * 32;
    const int x  = threadIdx.x;     // 0..31
    const int y  = threadIdx.y;     // 0..7
#pragma unroll
    for (int i = 0; i < 32; i += 8)
        tile[y + i][x] = v[((size_t)b * SEQ + s0 + y + i) * HID + d0 + x];
    __syncthreads();
#pragma unroll
    for (int i = 0; i < 32; i += 8) {
        float val = tile[x][y + i];
        bf16 h, l;
        split2(val, h, l);
        size_t o = ((size_t)b * HID + d0 + y + i) * SEQ + s0 + x;
        th[o] = h; tl[o] = l;
    }
}

// ---------------------------------------------------------------------------
// mma.sync m16n8k16 bf16 -> fp32
// ---------------------------------------------------------------------------
__device__ __forceinline__ void mma16816(float* c, const uint32_t* a, const uint32_t* b)
{
    asm("mma.sync.aligned.m16n8k16.row.col.f32.bf16.bf16.f32 "
        "{%0,%1,%2,%3}, {%4,%5,%6,%7}, {%8,%9}, {%0,%1,%2,%3};"
        : "+f"(c[0]), "+f"(c[1]), "+f"(c[2]), "+f"(c[3])
        : "r"(a[0]), "r"(a[1]), "r"(a[2]), "r"(a[3]), "r"(b[0]), "r"(b[1]));
}

// ---------------------------------------------------------------------------
// Dense tensor-core GEMM (3-term split): C = A@W + bias (+res)(+GELU)
// A:[M,K] split pair, W:[N,K] split pair. BM=BN=128, BK=16, 8 warps (2x4).
// SPLITOUT: write bf16 (h,l) pair instead of fp32.
// ---------------------------------------------------------------------------
template<int ACT, bool HASRES, bool SPLITOUT>
__global__ __launch_bounds__(256, 1)
void tc_gemm(const bf16* __restrict__ Ah, const bf16* __restrict__ Al,
             const bf16* __restrict__ WhT, const bf16* __restrict__ WlT,
             const float* __restrict__ bias, const float* __restrict__ res,
             float* __restrict__ C, bf16* __restrict__ Oh, bf16* __restrict__ Ol,
             int Ndim, int Kdim)
{
    __shared__ bf16 sAh[2][128][24];
    __shared__ bf16 sAl[2][128][24];
    __shared__ bf16 sBh[2][128][24];
    __shared__ bf16 sBl[2][128][24];

    const int tid  = threadIdx.x;
    const int row0 = blockIdx.y * 128;
    const int col0 = blockIdx.x * 128;
    const int lrow = tid >> 1;
    const int kofs = (tid & 1) * 8;

    const bf16* pAh = Ah  + (size_t)(row0 + lrow) * Kdim + kofs;
    const bf16* pAl = Al  + (size_t)(row0 + lrow) * Kdim + kofs;
    const bf16* pBh = WhT + (size_t)(col0 + lrow) * Kdim + kofs;
    const bf16* pBl = WlT + (size_t)(col0 + lrow) * Kdim + kofs;

    const int wid  = tid >> 5;
    const int m0   = (wid & 1) * 64;
    const int n0   = (wid >> 1) * 32;
    const int lane = tid & 31;
    const int gg   = lane >> 2;
    const int tg   = lane & 3;

    float acc[4][4][4];
#pragma unroll
    for (int i = 0; i < 4; i++)
#pragma unroll
        for (int j = 0; j < 4; j++)
#pragma unroll
            for (int t = 0; t < 4; t++) acc[i][j][t] = 0.f;

    {
        uint4 a_h = *reinterpret_cast<const uint4*>(pAh);
        uint4 a_l = *reinterpret_cast<const uint4*>(pAl);
        uint4 b_h = *reinterpret_cast<const uint4*>(pBh);
        uint4 b_l = *reinterpret_cast<const uint4*>(pBl);
        *reinterpret_cast<uint4*>(&sAh[0][lrow][kofs]) = a_h;
        *reinterpret_cast<uint4*>(&sAl[0][lrow][kofs]) = a_l;
        *reinterpret_cast<uint4*>(&sBh[0][lrow][kofs]) = b_h;
        *reinterpret_cast<uint4*>(&sBl[0][lrow][kofs]) = b_l;
    }
    __syncthreads();

    int s = 0;
    for (int k0 = 0; k0 < Kdim; k0 += 16) {
        const bool has_next = (k0 + 16 < Kdim);
        uint4 nAh, nAl, nBh, nBl;
        if (has_next) {
            nAh = *reinterpret_cast<const uint4*>(pAh + k0 + 16);
            nAl = *reinterpret_cast<const uint4*>(pAl + k0 + 16);
            nBh = *reinterpret_cast<const uint4*>(pBh + k0 + 16);
            nBl = *reinterpret_cast<const uint4*>(pBl + k0 + 16);
        }

        uint32_t afh[4][4], afl[4][4], bfh[4][2], bfl[4][2];
#pragma unroll
        for (int i = 0; i < 4; i++) {
            const int r = m0 + i * 16;
            afh[i][0] = *reinterpret_cast<const uint32_t*>(&sAh[s][r + gg    ][2 * tg    ]);
            afh[i][1] = *reinterpret_cast<const uint32_t*>(&sAh[s][r + 8 + gg][2 * tg    ]);
            afh[i][2] = *reinterpret_cast<const uint32_t*>(&sAh[s][r + gg    ][2 * tg + 8]);
            afh[i][3] = *reinterpret_cast<const uint32_t*>(&sAh[s][r + 8 + gg][2 * tg + 8]);
            afl[i][0] = *reinterpret_cast<const uint32_t*>(&sAl[s][r + gg    ][2 * tg    ]);
            afl[i][1] = *reinterpret_cast<const uint32_t*>(&sAl[s][r + 8 + gg][2 * tg    ]);
            afl[i][2] = *reinterpret_cast<const uint32_t*>(&sAl[s][r + gg    ][2 * tg + 8]);
            afl[i][3] = *reinterpret_cast<const uint32_t*>(&sAl[s][r + 8 + gg][2 * tg + 8]);
        }
#pragma unroll
        for (int j = 0; j < 4; j++) {
            const int c = n0 + j * 8;
            bfh[j][0] = *reinterpret_cast<const uint32_t*>(&sBh[s][c + gg][2 * tg    ]);
            bfh[j][1] = *reinterpret_cast<const uint32_t*>(&sBh[s][c + gg][2 * tg + 8]);
            bfl[j][0] = *reinterpret_cast<const uint32_t*>(&sBl[s][c + gg][2 * tg    ]);
            bfl[j][1] = *reinterpret_cast<const uint32_t*>(&sBl[s][c + gg][2 * tg + 8]);
        }

#pragma unroll
        for (int i = 0; i < 4; i++)
#pragma unroll
            for (int j = 0; j < 4; j++) {
                mma16816(acc[i][j], afh[i], bfh[j]);
                mma16816(acc[i][j], afh[i], bfl[j]);
                mma16816(acc[i][j], afl[i], bfh[j]);
            }

        if (has_next) {
            const int ns = s ^ 1;
            *reinterpret_cast<uint4*>(&sAh[ns][lrow][kofs]) = nAh;
            *reinterpret_cast<uint4*>(&sAl[ns][lrow][kofs]) = nAl;
            *reinterpret_cast<uint4*>(&sBh[ns][lrow][kofs]) = nBh;
            *reinterpret_cast<uint4*>(&sBl[ns][lrow][kofs]) = nBl;
            __syncthreads();
        }
        s ^= 1;
    }

#pragma unroll
    for (int i = 0; i < 4; i++) {
        const int r_lo = row0 + m0 + i * 16 + gg;
        const int r_hi = r_lo + 8;
#pragma unroll
        for (int j = 0; j < 4; j++) {
            const int c = col0 + n0 + j * 8 + 2 * tg;
            float2 b2 = *reinterpret_cast<const float2*>(bias + c);
            float v0 = acc[i][j][0] + b2.x;
            float v1 = acc[i][j][1] + b2.y;
            float v2 = acc[i][j][2] + b2.x;
            float v3 = acc[i][j][3] + b2.y;
            if (HASRES) {
                float2 r0 = *reinterpret_cast<const float2*>(res + (size_t)r_lo * Ndim + c);
                float2 r1 = *reinterpret_cast<const float2*>(res + (size_t)r_hi * Ndim + c);
                v0 += r0.x; v1 += r0.y; v2 += r1.x; v3 += r1.y;
            }
            if (ACT == 1) {
                v0 = 0.5f * v0 * (1.f + erff(v0 * 0.7071067811865475f));
                v1 = 0.5f * v1 * (1.f + erff(v1 * 0.7071067811865475f));
                v2 = 0.5f * v2 * (1.f + erff(v2 * 0.7071067811865475f));
                v3 = 0.5f * v3 * (1.f + erff(v3 * 0.7071067811865475f));
            }
            if (SPLITOUT) {
                bf16 h0, h1, h2, h3, l0, l1, l2, l3;
                split2(v0, h0, l0); split2(v1, h1, l1);
                split2(v2, h2, l2); split2(v3, h3, l3);
                *reinterpret_cast<__nv_bfloat162*>(Oh + (size_t)r_lo * Ndim + c) = __nv_bfloat162(h0, h1);
                *reinterpret_cast<__nv_bfloat162*>(Oh + (size_t)r_hi * Ndim + c) = __nv_bfloat162(h2, h3);
                *reinterpret_cast<__nv_bfloat162*>(Ol + (size_t)r_lo * Ndim + c) = __nv_bfloat162(l0, l1);
                *reinterpret_cast<__nv_bfloat162*>(Ol + (size_t)r_hi * Ndim + c) = __nv_bfloat162(l2, l3);
            } else {
                *reinterpret_cast<float2*>(C + (size_t)r_lo * Ndim + c) = make_float2(v0, v1);
                *reinterpret_cast<float2*>(C + (size_t)r_hi * Ndim + c) = make_float2(v2, v3);
            }
        }
    }
}

// ---------------------------------------------------------------------------
// QK^T scores via tensor cores: S = (Q.K^T)/8 + mask.  Per (b,h), K=64.
// ---------------------------------------------------------------------------
__global__ __launch_bounds__(256, 1)
void attn_scores_tc(const bf16* __restrict__ qh, const bf16* __restrict__ ql,
                    const bf16* __restrict__ kh, const bf16* __restrict__ kl,
                    const float* __restrict__ mask, float* __restrict__ sc)
{
    __shared__ bf16 sAh[2][128][24];
    __shared__ bf16 sAl[2][128][24];
    __shared__ bf16 sBh[2][128][24];
    __shared__ bf16 sBl[2][128][24];

    const int z = blockIdx.z;
    const int b = z / NHEAD, h = z % NHEAD;
    const int tid  = threadIdx.x;
    const int row0 = blockIdx.y * 128;
    const int col0 = blockIdx.x * 128;
    const int lrow = tid >> 1;
    const int kofs = (tid & 1) * 8;

    const size_t hoff = (size_t)h * HDIM;
    const bf16* pAh = qh + ((size_t)(b * SEQ + row0 + lrow)) * HID + hoff + kofs;
    const bf16* pAl = ql + ((size_t)(b * SEQ + row0 + lrow)) * HID + hoff + kofs;
    const bf16* pBh = kh + ((size_t)(b * SEQ + col0 + lrow)) * HID + hoff + kofs;
    const bf16* pBl = kl + ((size_t)(b * SEQ + col0 + lrow)) * HID + hoff + kofs;

    const int wid  = tid >> 5;
    const int m0   = (wid & 1) * 64;
    const int n0   = (wid >> 1) * 32;
    const int lane = tid & 31;
    const int gg   = lane >> 2;
    const int tg   = lane & 3;

    float acc[4][4][4];
#pragma unroll
    for (int i = 0; i < 4; i++)
#pragma unroll
        for (int j = 0; j < 4; j++)
#pragma unroll
            for (int t = 0; t < 4; t++) acc[i][j][t] = 0.f;

    {
        uint4 a_h = *reinterpret_cast<const uint4*>(pAh);
        uint4 a_l = *reinterpret_cast<const uint4*>(pAl);
        uint4 b_h = *reinterpret_cast<const uint4*>(pBh);
        uint4 b_l = *reinterpret_cast<const uint4*>(pBl);
        *reinterpret_cast<uint4*>(&sAh[0][lrow][kofs]) = a_h;
        *reinterpret_cast<uint4*>(&sAl[0][lrow][kofs]) = a_l;
        *reinterpret_cast<uint4*>(&sBh[0][lrow][kofs]) = b_h;
        *reinterpret_cast<uint4*>(&sBl[0][lrow][kofs]) = b_l;
    }
    __syncthreads();

    int s = 0;
#pragma unroll
    for (int k0 = 0; k0 < HDIM; k0 += 16) {
        const bool has_next = (k0 + 16 < HDIM);
        uint4 nAh, nAl, nBh, nBl;
        if (has_next) {
            nAh = *reinterpret_cast<const uint4*>(pAh + k0 + 16);
            nAl = *reinterpret_cast<const uint4*>(pAl + k0 + 16);
            nBh = *reinterpret_cast<const uint4*>(pBh + k0 + 16);
            nBl = *reinterpret_cast<const uint4*>(pBl + k0 + 16);
        }

        uint32_t afh[4][4], afl[4][4], bfh[4][2], bfl[4][2];
#pragma unroll
        for (int i = 0; i < 4; i++) {
            const int r = m0 + i * 16;
            afh[i][0] = *reinterpret_cast<const uint32_t*>(&sAh[s][r + gg    ][2 * tg    ]);
            afh[i][1] = *reinterpret_cast<const uint32_t*>(&sAh[s][r + 8 + gg][2 * tg    ]);
            afh[i][2] = *reinterpret_cast<const uint32_t*>(&sAh[s][r + gg    ][2 * tg + 8]);
            afh[i][3] = *reinterpret_cast<const uint32_t*>(&sAh[s][r + 8 + gg][2 * tg + 8]);
            afl[i][0] = *reinterpret_cast<const uint32_t*>(&sAl[s][r + gg    ][2 * tg    ]);
            afl[i][1] = *reinterpret_cast<const uint32_t*>(&sAl[s][r + 8 + gg][2 * tg    ]);
            afl[i][2] = *reinterpret_cast<const uint32_t*>(&sAl[s][r + gg    ][2 * tg + 8]);
            afl[i][3] = *reinterpret_cast<const uint32_t*>(&sAl[s][r + 8 + gg][2 * tg + 8]);
        }
#pragma unroll
        for (int j = 0; j < 4; j++) {
            const int c = n0 + j * 8;
            bfh[j][0] = *reinterpret_cast<const uint32_t*>(&sBh[s][c + gg][2 * tg    ]);
            bfh[j][1] = *reinterpret_cast<const uint32_t*>(&sBh[s][c + gg][2 * tg + 8]);
            bfl[j][0] = *reinterpret_cast<const uint32_t*>(&sBl[s][c + gg][2 * tg    ]);
            bfl[j][1] = *reinterpret_cast<const uint32_t*>(&sBl[s][c + gg][2 * tg + 8]);
        }

#pragma unroll
        for (int i = 0; i < 4; i++)
#pragma unroll
            for (int j = 0; j < 4; j++) {
                mma16816(acc[i][j], afh[i], bfh[j]);
                mma16816(acc[i][j], afh[i], bfl[j]);
                mma16816(acc[i][j], afl[i], bfh[j]);
            }

        if (has_next) {
            const int ns = s ^ 1;
            *reinterpret_cast<uint4*>(&sAh[ns][lrow][kofs]) = nAh;
            *reinterpret_cast<uint4*>(&sAl[ns][lrow][kofs]) = nAl;
            *reinterpret_cast<uint4*>(&sBh[ns][lrow][kofs]) = nBh;
            *reinterpret_cast<uint4*>(&sBl[ns][lrow][kofs]) = nBl;
            __syncthreads();
        }
        s ^= 1;
    }

    float* Cb = sc + (size_t)z * SEQ * SEQ;
    const float* mb = mask + (size_t)b * SEQ;
#pragma unroll
    for (int i = 0; i < 4; i++) {
        const int r_lo = row0 + m0 + i * 16 + gg;
        const int r_hi = r_lo + 8;
#pragma unroll
        for (int j = 0; j < 4; j++) {
            const int c = col0 + n0 + j * 8 + 2 * tg;
            float2 m2 = *reinterpret_cast<const float2*>(mb + c);
            float v0 = acc[i][j][0] * 0.125f + m2.x;
            float v1 = acc[i][j][1] * 0.125f + m2.y;
            float v2 = acc[i][j][2] * 0.125f + m2.x;
            float v3 = acc[i][j][3] * 0.125f + m2.y;
            *reinterpret_cast<float2*>(Cb + (size_t)r_lo * SEQ + c) = make_float2(v0, v1);
            *reinterpret_cast<float2*>(Cb + (size_t)r_hi * SEQ + c) = make_float2(v2, v3);
        }
    }
}

// ---------------------------------------------------------------------------
// Row softmax over 1024 keys -> split bf16 probs.
// ---------------------------------------------------------------------------
__global__ __launch_bounds__(256)
void softmax_bf16(const float* __restrict__ sc, bf16* __restrict__ ph,
                  bf16* __restrict__ pl)
{
    const size_t base = (size_t)blockIdx.x * SEQ;
    const float* p = sc + base;
    const int tid = threadIdx.x;
    __shared__ float red[8];

    float4 v = *reinterpret_cast<const float4*>(p + tid * 4);
    float mx = fmaxf(fmaxf(v.x, v.y), fmaxf(v.z, v.w));
#pragma unroll
    for (int o = 16; o; o >>= 1) mx = fmaxf(mx, __shfl_xor_sync(0xffffffffu, mx, o));
    if ((tid & 31) == 0) red[tid >> 5] = mx;
    __syncthreads();
    float m = red[0];
#pragma unroll
    for (int i = 1; i < 8; i++) m = fmaxf(m, red[i]);
    __syncthreads();

    v.x = expf(v.x - m); v.y = expf(v.y - m);
    v.z = expf(v.z - m); v.w = expf(v.w - m);
    float s = v.x + v.y + v.z + v.w;
#pragma unroll
    for (int o = 16; o; o >>= 1) s += __shfl_xor_sync(0xffffffffu, s, o);
    if ((tid & 31) == 0) red[tid >> 5] = s;
    __syncthreads();
    float tot = 0.f;
#pragma unroll
    for (int i = 0; i < 8; i++) tot += red[i];
    const float inv = 1.f / tot;
    v.x *= inv; v.y *= inv; v.z *= inv; v.w *= inv;

    bf16 h0, h1, h2, h3, l0, l1, l2, l3;
    split2(v.x, h0, l0); split2(v.y, h1, l1);
    split2(v.z, h2, l2); split2(v.w, h3, l3);
    __nv_bfloat162* hp = reinterpret_cast<__nv_bfloat162*>(ph + base + tid * 4);
    __nv_bfloat162* lp = reinterpret_cast<__nv_bfloat162*>(pl + base + tid * 4);
    hp[0] = __nv_bfloat162(h0, h1); hp[1] = __nv_bfloat162(h2, h3);
    lp[0] = __nv_bfloat162(l0, l1); lp[1] = __nv_bfloat162(l2, l3);
}

// ---------------------------------------------------------------------------
// ctx = P @ V via tensor cores, per (b,h). M=1024, N=64, K=1024.
// P split [S,S] lda=SEQ; V^T split [HID][SEQ] ldb=SEQ. BM=128, BN=64.
// 8 warps (4m x 2n), warp tile 32x32. Output: split bf16 ctx [B,S,HID].
// ---------------------------------------------------------------------------
__global__ __launch_bounds__(256, 1)
void attn_pv_tc(const bf16* __restrict__ ph, const bf16* __restrict__ pl,
                const bf16* __restrict__ vth, const bf16* __restrict__ vtl,
                bf16* __restrict__ ch, bf16* __restrict__ cl)
{
    __shared__ bf16 sAh[2][128][24];
    __shared__ bf16 sAl[2][128][24];
    __shared__ bf16 sBh[2][64][24];
    __shared__ bf16 sBl[2][64][24];

    const int z = blockIdx.y;
    const int b = z / NHEAD, h = z % NHEAD;
    const int tid  = threadIdx.x;
    const int row0 = blockIdx.x * 128;

    const int lrow = tid >> 1;
    const int akof = (tid & 1) * 8;
    const int brow = tid >> 2;          // 0..63
    const int bkof = (tid & 3) * 4;     // 0,4,8,12

    const bf16* pAh = ph  + (size_t)z * SEQ * SEQ + (size_t)(row0 + lrow) * SEQ + akof;
    const bf16* pAl = pl  + (size_t)z * SEQ * SEQ + (size_t)(row0 + lrow) * SEQ + akof;
    const bf16* pBh = vth + ((size_t)b * HID + h * HDIM + brow) * SEQ + bkof;
    const bf16* pBl = vtl + ((size_t)b * HID + h * HDIM + brow) * SEQ + bkof;

    const int wid  = tid >> 5;
    const int m0   = (wid & 3) * 32;
    const int n0   = (wid >> 2) * 32;
    const int lane = tid & 31;
    const int gg   = lane >> 2;
    const int tg   = lane & 3;

    float acc[2][4][4];
#pragma unroll
    for (int i = 0; i < 2; i++)
#pragma unroll
        for (int j = 0; j < 4; j++)
#pragma unroll
            for (int t = 0; t < 4; t++) acc[i][j][t] = 0.f;

    {
        uint4 a_h = *reinterpret_cast<const uint4*>(pAh);
        uint4 a_l = *reinterpret_cast<const uint4*>(pAl);
        uint2 b_h = *reinterpret_cast<const uint2*>(pBh);
        uint2 b_l = *reinterpret_cast<const uint2*>(pBl);
        *reinterpret_cast<uint4*>(&sAh[0][lrow][akof]) = a_h;
        *reinterpret_cast<uint4*>(&sAl[0][lrow][akof]) = a_l;
        *reinterpret_cast<uint2*>(&sBh[0][brow][bkof]) = b_h;
        *reinterpret_cast<uint2*>(&sBl[0][brow][bkof]) = b_l;
    }
    __syncthreads();

    int s = 0;
    for (int k0 = 0; k0 < SEQ; k0 += 16) {
        const bool has_next = (k0 + 16 < SEQ);
        uint4 nAh, nAl;
        uint2 nBh, nBl;
        if (has_next) {
            nAh = *reinterpret_cast<const uint4*>(pAh + k0 + 16);
            nAl = *reinterpret_cast<const uint4*>(pAl + k0 + 16);
            nBh = *reinterpret_cast<const uint2*>(pBh + k0 + 16);
            nBl = *reinterpret_cast<const uint2*>(pBl + k0 + 16);
        }

        uint32_t afh[2][4], afl[2][4], bfh[4][2], bfl[4][2];
#pragma unroll
        for (int i = 0; i < 2; i++) {
            const int r = m0 + i * 16;
            afh[i][0] = *reinterpret_cast<const uint32_t*>(&sAh[s][r + gg    ][2 * tg    ]);
            afh[i][1] = *reinterpret_cast<const uint32_t*>(&sAh[s][r + 8 + gg][2 * tg    ]);
            afh[i][2] = *reinterpret_cast<const uint32_t*>(&sAh[s][r + gg    ][2 * tg + 8]);
            afh[i][3] = *reinterpret_cast<const uint32_t*>(&sAh[s][r + 8 + gg][2 * tg + 8]);
            afl[i][0] = *reinterpret_cast<const uint32_t*>(&sAl[s][r + gg    ][2 * tg    ]);
            afl[i][1] = *reinterpret_cast<const uint32_t*>(&sAl[s][r + 8 + gg][2 * tg    ]);
            afl[i][2] = *reinterpret_cast<const uint32_t*>(&sAl[s][r + gg    ][2 * tg + 8]);
            afl[i][3] = *reinterpret_cast<const uint32_t*>(&sAl[s][r + 8 + gg][2 * tg + 8]);
        }
#pragma unroll
        for (int j = 0; j < 4; j++) {
            const int c = n0 + j * 8;
            bfh[j][0] = *reinterpret_cast<const uint32_t*>(&sBh[s][c + gg][2 * tg    ]);
            bfh[j][1] = *reinterpret_cast<const uint32_t*>(&sBh[s][c + gg][2 * tg + 8]);
            bfl[j][0] = *reinterpret_cast<const uint32_t*>(&sBl[s][c + gg][2 * tg    ]);
            bfl[j][1] = *reinterpret_cast<const uint32_t*>(&sBl[s][c + gg][2 * tg + 8]);
        }

#pragma unroll
        for (int i = 0; i < 2; i++)
#pragma unroll
            for (int j = 0; j < 4; j++) {
                mma16816(acc[i][j], afh[i], bfh[j]);
                mma16816(acc[i][j], afh[i], bfl[j]);
                mma16816(acc[i][j], afl[i], bfh[j]);
            }

        if (has_next) {
            const int ns = s ^ 1;
            *reinterpret_cast<uint4*>(&sAh[ns][lrow][akof]) = nAh;
            *reinterpret_cast<uint4*>(&sAl[ns][lrow][akof]) = nAl;
            *reinterpret_cast<uint2*>(&sBh[ns][brow][bkof]) = nBh;
            *reinterpret_cast<uint2*>(&sBl[ns][brow][bkof]) = nBl;
            __syncthreads();
        }
        s ^= 1;
    }

#pragma unroll
    for (int i = 0; i < 2; i++) {
        const int r_lo = row0 + m0 + i * 16 + gg;
        const int r_hi = r_lo + 8;
#pragma unroll
        for (int j = 0; j < 4; j++) {
            const int c = h * HDIM + n0 + j * 8 + 2 * tg;
            bf16 h0, h1, h2, h3, l0, l1, l2, l3;
            split2(acc[i][j][0], h0, l0); split2(acc[i][j][1], h1, l1);
            split2(acc[i][j][2], h2, l2); split2(acc[i][j][3], h3, l3);
            size_t o_lo = ((size_t)(b * SEQ) + r_lo) * HID + c;
            size_t o_hi = ((size_t)(b * SEQ) + r_hi) * HID + c;
            *reinterpret_cast<__nv_bfloat162*>(ch + o_lo) = __nv_bfloat162(h0, h1);
            *reinterpret_cast<__nv_bfloat162*>(ch + o_hi) = __nv_bfloat162(h2, h3);
            *reinterpret_cast<__nv_bfloat162*>(cl + o_lo) = __nv_bfloat162(l0, l1);
            *reinterpret_cast<__nv_bfloat162*>(cl + o_hi) = __nv_bfloat162(l2, l3);
        }
    }
}

// ---------------------------------------------------------------------------
// LayerNorm over HID=768, bf16 split outputs fused.
// ---------------------------------------------------------------------------
__global__ __launch_bounds__(256)
void layernorm_split(const float* __restrict__ x, const float* __restrict__ gam,
                     const float* __restrict__ bet, float* __restrict__ out,
                     bf16* __restrict__ oh, bf16* __restrict__ ol)
{
    const int row = blockIdx.x;
    const float* xr = x + (size_t)row * HID;
    const int tid = threadIdx.x;
    __shared__ float rs_[8], rq_[8];

    float v0 = xr[tid], v1 = xr[tid + 256], v2 = xr[tid + 512];
    float s  = v0 + v1 + v2;
    float sq = v0 * v0 + v1 * v1 + v2 * v2;
#pragma unroll
    for (int o = 16; o; o >>= 1) {
        s  += __shfl_xor_sync(0xffffffffu, s,  o);
        sq += __shfl_xor_sync(0xffffffffu, sq, o);
    }
    if ((tid & 31) == 0) { rs_[tid >> 5] = s; rq_[tid >> 5] = sq; }
    __syncthreads();
    float ts = 0.f, tq = 0.f;
#pragma unroll
    for (int i = 0; i < 8; i++) { ts += rs_[i]; tq += rq_[i]; }
    const float mean = ts * (1.f / HID);
    const float var  = tq * (1.f / HID) - mean * mean;
    const float rstd = rsqrtf(var + 1e-5f);

    float* o = out + (size_t)row * HID;
    float r0 = (v0 - mean) * rstd * gam[tid]       + bet[tid];
    float r1 = (v1 - mean) * rstd * gam[tid + 256] + bet[tid + 256];
    float r2 = (v2 - mean) * rstd * gam[tid + 512] + bet[tid + 512];
    o[tid] = r0; o[tid + 256] = r1; o[tid + 512] = r2;

    bf16 h, l;
    split2(r0, h, l); oh[(size_t)row * HID + tid]       = h; ol[(size_t)row * HID + tid]       = l;
    split2(r1, h, l); oh[(size_t)row * HID + tid + 256] = h; ol[(size_t)row * HID + tid + 256] = l;
    split2(r2, h, l); oh[(size_t)row * HID + tid + 512] = h; ol[(size_t)row * HID + tid + 512] = l;
}

// ---------------------------------------------------------------------------
// Launcher
// ---------------------------------------------------------------------------
extern "C" void kernel_launch(void* const* d_in, const int* in_sizes, int n_in,
                              void* d_out, int out_size)
{
    (void)in_sizes; (void)n_in; (void)out_size;
    const float* hs    = (const float*)d_in[0];
    const float* mask  = (const float*)d_in[1];
    const float* q_w   = (const float*)d_in[2];
    const float* q_b   = (const float*)d_in[3];
    const float* k_w   = (const float*)d_in[4];
    const float* k_b   = (const float*)d_in[5];
    const float* v_w   = (const float*)d_in[6];
    const float* v_b   = (const float*)d_in[7];
    const float* ao_w  = (const float*)d_in[8];
    const float* ao_b  = (const float*)d_in[9];
    const float* ln1_g = (const float*)d_in[10];
    const float* ln1_b = (const float*)d_in[11];
    const float* ff1_w = (const float*)d_in[12];
    const float* ff1_b = (const float*)d_in[13];
    const float* ff2_w = (const float*)d_in[14];
    const float* ff2_b = (const float*)d_in[15];
    const float* ln2_g = (const float*)d_in[16];
    const float* ln2_b = (const float*)d_in[17];
    float* out = (float*)d_out;

    float *x, *v, *sc, *y, *attn, *y2;
    cudaGetSymbolAddress((void**)&x,    g_x);
    cudaGetSymbolAddress((void**)&v,    g_v);
    cudaGetSymbolAddress((void**)&sc,   g_sc);
    cudaGetSymbolAddress((void**)&y,    g_y);
    cudaGetSymbolAddress((void**)&attn, g_attn);
    cudaGetSymbolAddress((void**)&y2,   g_y2);

    bf16 *xh,*xl,*qh,*ql,*kh,*kl,*vth,*vtl,*ch,*cl,*ah,*al,*fh,*fl,*ph,*pl;
    cudaGetSymbolAddress((void**)&xh,  g_xh);  cudaGetSymbolAddress((void**)&xl,  g_xl);
    cudaGetSymbolAddress((void**)&qh,  g_qh);  cudaGetSymbolAddress((void**)&ql,  g_ql);
    cudaGetSymbolAddress((void**)&kh,  g_kh);  cudaGetSymbolAddress((void**)&kl,  g_kl);
    cudaGetSymbolAddress((void**)&vth, g_vth); cudaGetSymbolAddress((void**)&vtl, g_vtl);
    cudaGetSymbolAddress((void**)&ch,  g_ch);  cudaGetSymbolAddress((void**)&cl,  g_cl);
    cudaGetSymbolAddress((void**)&ah,  g_ah);  cudaGetSymbolAddress((void**)&al,  g_al);
    cudaGetSymbolAddress((void**)&fh,  g_fh);  cudaGetSymbolAddress((void**)&fl,  g_fl);
    cudaGetSymbolAddress((void**)&ph,  g_ph);  cudaGetSymbolAddress((void**)&pl,  g_pl);

    bf16 *qwh,*qwl,*kwh,*kwl,*vwh,*vwl,*awh,*awl,*f1h,*f1l,*f2h,*f2l;
    cudaGetSymbolAddress((void**)&qwh, g_qwh); cudaGetSymbolAddress((void**)&qwl, g_qwl);
    cudaGetSymbolAddress((void**)&kwh, g_kwh); cudaGetSymbolAddress((void**)&kwl, g_kwl);
    cudaGetSymbolAddress((void**)&vwh, g_vwh); cudaGetSymbolAddress((void**)&vwl, g_vwl);
    cudaGetSymbolAddress((void**)&awh, g_awh); cudaGetSymbolAddress((void**)&awl, g_awl);
    cudaGetSymbolAddress((void**)&f1h, g_f1h); cudaGetSymbolAddress((void**)&f1l, g_f1l);
    cudaGetSymbolAddress((void**)&f2h, g_f2h); cudaGetSymbolAddress((void**)&f2l, g_f2l);

    const int nHH = HID * HID, nHF = HID * FFDIM;
    split_wT<<<(nHH + 255) / 256, 256>>>(q_w,  qwh, qwl, HID, HID);
    split_wT<<<(nHH + 255) / 256, 256>>>(k_w,  kwh, kwl, HID, HID);
    split_wT<<<(nHH + 255) / 256, 256>>>(v_w,  vwh, vwl, HID, HID);
    split_wT<<<(nHH + 255) / 256, 256>>>(ao_w, awh, awl, HID, HID);
    split_wT<<<(nHF + 255) / 256, 256>>>(ff1_w, f1h, f1l, HID, FFDIM);
    split_wT<<<(nHF + 255) / 256, 256>>>(ff2_w, f2h, f2l, FFDIM, HID);

    const dim3 gH (HID   / 128, MTOK / 128);
    const dim3 gFF(FFDIM / 128, MTOK / 128);
    const dim3 gSc(SEQ / 128, SEQ / 128, NBH);
    const dim3 gPV(SEQ / 128, NBH);
    const dim3 gVT(SEQ / 32, HID / 32, BATCH);
    const int nACT = MTOK * HID;

    split_act<<<(nACT / 4 + 255) / 256, 256>>>(hs, xh, xl, nACT);

    for (int l = 0; l < L_LAYERS; l++) {
        const float* xin = (l == 0) ? hs : x;

        tc_gemm<0, false, true><<<gH, 256>>>(xh, xl, qwh, qwl, q_b, nullptr,
                                             nullptr, qh, ql, HID, HID);
        tc_gemm<0, false, true><<<gH, 256>>>(xh, xl, kwh, kwl, k_b, nullptr,
                                             nullptr, kh, kl, HID, HID);
        tc_gemm<0, false, false><<<gH, 256>>>(xh, xl, vwh, vwl, v_b, nullptr,
                                              v, nullptr, nullptr, HID, HID);
        split_vT<<<gVT, dim3(32, 8)>>>(v, vth, vtl);

        attn_scores_tc<<<gSc, 256>>>(qh, ql, kh, kl, mask, sc);
        softmax_bf16<<<NBH * SEQ, 256>>>(sc, ph, pl);
        attn_pv_tc<<<gPV, 256>>>(ph, pl, vth, vtl, ch, cl);

        tc_gemm<0, true, false><<<gH, 256>>>(ch, cl, awh, awl, ao_b, xin,
                                             y, nullptr, nullptr, HID, HID);
        layernorm_split<<<MTOK, 256>>>(y, ln1_g, ln1_b, attn, ah, al);

        tc_gemm<1, false, true><<<gFF, 256>>>(ah, al, f1h, f1l, ff1_b, nullptr,
                                              nullptr, fh, fl, FFDIM, HID);
        tc_gemm<0, true, false><<<gH, 256>>>(fh, fl, f2h, f2l, ff2_b, attn,
                                             y2, nullptr, nullptr, HID, FFDIM);

        float* xo = (l == L_LAYERS - 1) ? out : x;
        layernorm_split<<<MTOK, 256>>>(y2, ln2_g, ln2_b, xo, xh, xl);
    }
}

// round 9
// speedup vs baseline: 1.2190x; 1.1221x over previous
#include <cuda_runtime.h>
#include <cuda_bf16.h>
#include <math.h>
#include <stdint.h>

#define L_LAYERS 6
#define BATCH    4
#define SEQ      1024
#define HID      768
#define NHEAD    12
#define HDIM     64
#define FFDIM    3072
#define MTOK     (BATCH*SEQ)      // 4096 tokens
#define NBH      (BATCH*NHEAD)    // 48
#define FBM      128              // flash: query rows per CTA
#define FBN      64               // flash: keys per iteration

typedef __nv_bfloat16 bf16;

// ---------------------------------------------------------------------------
// Scratch (device globals)
// ---------------------------------------------------------------------------
__device__ float g_x   [MTOK*HID];
__device__ float g_v   [MTOK*HID];
__device__ float g_y   [MTOK*HID];
__device__ float g_attn[MTOK*HID];
__device__ float g_y2  [MTOK*HID];

__device__ bf16 g_xh[MTOK*HID],  g_xl[MTOK*HID];
__device__ bf16 g_qh[MTOK*HID],  g_ql[MTOK*HID];
__device__ bf16 g_kh[MTOK*HID],  g_kl[MTOK*HID];
__device__ bf16 g_vth[MTOK*HID], g_vtl[MTOK*HID];   // V^T per batch [HID][SEQ]
__device__ bf16 g_ch[MTOK*HID],  g_cl[MTOK*HID];    // ctx split
__device__ bf16 g_ah[MTOK*HID],  g_al[MTOK*HID];    // LN1 split
__device__ bf16 g_fh[MTOK*FFDIM],g_fl[MTOK*FFDIM];  // FF hidden split

// weights split, transposed [N,K]
__device__ bf16 g_qwh[HID*HID],   g_qwl[HID*HID];
__device__ bf16 g_kwh[HID*HID],   g_kwl[HID*HID];
__device__ bf16 g_vwh[HID*HID],   g_vwl[HID*HID];
__device__ bf16 g_awh[HID*HID],   g_awl[HID*HID];
__device__ bf16 g_f1h[HID*FFDIM], g_f1l[HID*FFDIM];
__device__ bf16 g_f2h[FFDIM*HID], g_f2l[FFDIM*HID];

__device__ __forceinline__ void split2(float v, bf16& h, bf16& l)
{
    h = __float2bfloat16_rn(v);
    l = __float2bfloat16_rn(v - __bfloat162float(h));
}

__device__ __forceinline__ uint32_t pack_bf2(bf16 a, bf16 b)
{
    __nv_bfloat162 t(a, b);
    return *reinterpret_cast<uint32_t*>(&t);
}

// ---------------------------------------------------------------------------
// Split helpers
// ---------------------------------------------------------------------------
__global__ __launch_bounds__(256)
void split_act(const float* __restrict__ x, bf16* __restrict__ h,
               bf16* __restrict__ l, int n)
{
    int i = (blockIdx.x * 256 + threadIdx.x) * 4;
    if (i >= n) return;
    float4 v = *reinterpret_cast<const float4*>(x + i);
    bf16 h0, h1, h2, h3, l0, l1, l2, l3;
    split2(v.x, h0, l0); split2(v.y, h1, l1);
    split2(v.z, h2, l2); split2(v.w, h3, l3);
    __nv_bfloat162* hp = reinterpret_cast<__nv_bfloat162*>(h + i);
    __nv_bfloat162* lp = reinterpret_cast<__nv_bfloat162*>(l + i);
    hp[0] = __nv_bfloat162(h0, h1); hp[1] = __nv_bfloat162(h2, h3);
    lp[0] = __nv_bfloat162(l0, l1); lp[1] = __nv_bfloat162(l2, l3);
}

// W[K,N] row-major -> split, transposed to [N,K]
__global__ __launch_bounds__(256)
void split_wT(const float* __restrict__ W, bf16* __restrict__ hT,
              bf16* __restrict__ lT, int K, int N)
{
    int idx = blockIdx.x * 256 + threadIdx.x;
    if (idx >= K * N) return;
    int k = idx / N, n = idx - k * N;
    bf16 h, l;
    split2(W[idx], h, l);
    hT[(size_t)n * K + k] = h;
    lT[(size_t)n * K + k] = l;
}

// V [B,S,HID] fp32 -> per-batch transposed split [B][HID][SEQ]
__global__ __launch_bounds__(256)
void split_vT(const float* __restrict__ v, bf16* __restrict__ th,
              bf16* __restrict__ tl)
{
    __shared__ float tile[32][33];
    const int b  = blockIdx.z;
    const int s0 = blockIdx.x * 32;
    const int d0 = blockIdx.y * 32;
    const int x  = threadIdx.x;     // 0..31
    const int y  = threadIdx.y;     // 0..7
#pragma unroll
    for (int i = 0; i < 32; i += 8)
        tile[y + i][x] = v[((size_t)b * SEQ + s0 + y + i) * HID + d0 + x];
    __syncthreads();
#pragma unroll
    for (int i = 0; i < 32; i += 8) {
        float val = tile[x][y + i];
        bf16 h, l;
        split2(val, h, l);
        size_t o = ((size_t)b * HID + d0 + y + i) * SEQ + s0 + x;
        th[o] = h; tl[o] = l;
    }
}

// ---------------------------------------------------------------------------
// mma.sync m16n8k16 bf16 -> fp32
// ---------------------------------------------------------------------------
__device__ __forceinline__ void mma16816(float* c, const uint32_t* a, const uint32_t* b)
{
    asm("mma.sync.aligned.m16n8k16.row.col.f32.bf16.bf16.f32 "
        "{%0,%1,%2,%3}, {%4,%5,%6,%7}, {%8,%9}, {%0,%1,%2,%3};"
        : "+f"(c[0]), "+f"(c[1]), "+f"(c[2]), "+f"(c[3])
        : "r"(a[0]), "r"(a[1]), "r"(a[2]), "r"(a[3]), "r"(b[0]), "r"(b[1]));
}

// ---------------------------------------------------------------------------
// Dense tensor-core GEMM (3-term split): C = A@W + bias (+res)(+GELU)
// A:[M,K] split pair, W:[N,K] split pair. BM=BN=128, BK=16, 8 warps (2x4).
// SPLITOUT: write bf16 (h,l) pair instead of fp32.
// ---------------------------------------------------------------------------
template<int ACT, bool HASRES, bool SPLITOUT>
__global__ __launch_bounds__(256, 1)
void tc_gemm(const bf16* __restrict__ Ah, const bf16* __restrict__ Al,
             const bf16* __restrict__ WhT, const bf16* __restrict__ WlT,
             const float* __restrict__ bias, const float* __restrict__ res,
             float* __restrict__ C, bf16* __restrict__ Oh, bf16* __restrict__ Ol,
             int Ndim, int Kdim)
{
    __shared__ bf16 sAh[2][128][24];
    __shared__ bf16 sAl[2][128][24];
    __shared__ bf16 sBh[2][128][24];
    __shared__ bf16 sBl[2][128][24];

    const int tid  = threadIdx.x;
    const int row0 = blockIdx.y * 128;
    const int col0 = blockIdx.x * 128;
    const int lrow = tid >> 1;
    const int kofs = (tid & 1) * 8;

    const bf16* pAh = Ah  + (size_t)(row0 + lrow) * Kdim + kofs;
    const bf16* pAl = Al  + (size_t)(row0 + lrow) * Kdim + kofs;
    const bf16* pBh = WhT + (size_t)(col0 + lrow) * Kdim + kofs;
    const bf16* pBl = WlT + (size_t)(col0 + lrow) * Kdim + kofs;

    const int wid  = tid >> 5;
    const int m0   = (wid & 1) * 64;
    const int n0   = (wid >> 1) * 32;
    const int lane = tid & 31;
    const int gg   = lane >> 2;
    const int tg   = lane & 3;

    float acc[4][4][4];
#pragma unroll
    for (int i = 0; i < 4; i++)
#pragma unroll
        for (int j = 0; j < 4; j++)
#pragma unroll
            for (int t = 0; t < 4; t++) acc[i][j][t] = 0.f;

    {
        uint4 a_h = *reinterpret_cast<const uint4*>(pAh);
        uint4 a_l = *reinterpret_cast<const uint4*>(pAl);
        uint4 b_h = *reinterpret_cast<const uint4*>(pBh);
        uint4 b_l = *reinterpret_cast<const uint4*>(pBl);
        *reinterpret_cast<uint4*>(&sAh[0][lrow][kofs]) = a_h;
        *reinterpret_cast<uint4*>(&sAl[0][lrow][kofs]) = a_l;
        *reinterpret_cast<uint4*>(&sBh[0][lrow][kofs]) = b_h;
        *reinterpret_cast<uint4*>(&sBl[0][lrow][kofs]) = b_l;
    }
    __syncthreads();

    int s = 0;
    for (int k0 = 0; k0 < Kdim; k0 += 16) {
        const bool has_next = (k0 + 16 < Kdim);
        uint4 nAh, nAl, nBh, nBl;
        if (has_next) {
            nAh = *reinterpret_cast<const uint4*>(pAh + k0 + 16);
            nAl = *reinterpret_cast<const uint4*>(pAl + k0 + 16);
            nBh = *reinterpret_cast<const uint4*>(pBh + k0 + 16);
            nBl = *reinterpret_cast<const uint4*>(pBl + k0 + 16);
        }

        uint32_t afh[4][4], afl[4][4], bfh[4][2], bfl[4][2];
#pragma unroll
        for (int i = 0; i < 4; i++) {
            const int r = m0 + i * 16;
            afh[i][0] = *reinterpret_cast<const uint32_t*>(&sAh[s][r + gg    ][2 * tg    ]);
            afh[i][1] = *reinterpret_cast<const uint32_t*>(&sAh[s][r + 8 + gg][2 * tg    ]);
            afh[i][2] = *reinterpret_cast<const uint32_t*>(&sAh[s][r + gg    ][2 * tg + 8]);
            afh[i][3] = *reinterpret_cast<const uint32_t*>(&sAh[s][r + 8 + gg][2 * tg + 8]);
            afl[i][0] = *reinterpret_cast<const uint32_t*>(&sAl[s][r + gg    ][2 * tg    ]);
            afl[i][1] = *reinterpret_cast<const uint32_t*>(&sAl[s][r + 8 + gg][2 * tg    ]);
            afl[i][2] = *reinterpret_cast<const uint32_t*>(&sAl[s][r + gg    ][2 * tg + 8]);
            afl[i][3] = *reinterpret_cast<const uint32_t*>(&sAl[s][r + 8 + gg][2 * tg + 8]);
        }
#pragma unroll
        for (int j = 0; j < 4; j++) {
            const int c = n0 + j * 8;
            bfh[j][0] = *reinterpret_cast<const uint32_t*>(&sBh[s][c + gg][2 * tg    ]);
            bfh[j][1] = *reinterpret_cast<const uint32_t*>(&sBh[s][c + gg][2 * tg + 8]);
            bfl[j][0] = *reinterpret_cast<const uint32_t*>(&sBl[s][c + gg][2 * tg    ]);
            bfl[j][1] = *reinterpret_cast<const uint32_t*>(&sBl[s][c + gg][2 * tg + 8]);
        }

#pragma unroll
        for (int i = 0; i < 4; i++)
#pragma unroll
            for (int j = 0; j < 4; j++) {
                mma16816(acc[i][j], afh[i], bfh[j]);
                mma16816(acc[i][j], afh[i], bfl[j]);
                mma16816(acc[i][j], afl[i], bfh[j]);
            }

        if (has_next) {
            const int ns = s ^ 1;
            *reinterpret_cast<uint4*>(&sAh[ns][lrow][kofs]) = nAh;
            *reinterpret_cast<uint4*>(&sAl[ns][lrow][kofs]) = nAl;
            *reinterpret_cast<uint4*>(&sBh[ns][lrow][kofs]) = nBh;
            *reinterpret_cast<uint4*>(&sBl[ns][lrow][kofs]) = nBl;
            __syncthreads();
        }
        s ^= 1;
    }

#pragma unroll
    for (int i = 0; i < 4; i++) {
        const int r_lo = row0 + m0 + i * 16 + gg;
        const int r_hi = r_lo + 8;
#pragma unroll
        for (int j = 0; j < 4; j++) {
            const int c = col0 + n0 + j * 8 + 2 * tg;
            float2 b2 = *reinterpret_cast<const float2*>(bias + c);
            float v0 = acc[i][j][0] + b2.x;
            float v1 = acc[i][j][1] + b2.y;
            float v2 = acc[i][j][2] + b2.x;
            float v3 = acc[i][j][3] + b2.y;
            if (HASRES) {
                float2 r0 = *reinterpret_cast<const float2*>(res + (size_t)r_lo * Ndim + c);
                float2 r1 = *reinterpret_cast<const float2*>(res + (size_t)r_hi * Ndim + c);
                v0 += r0.x; v1 += r0.y; v2 += r1.x; v3 += r1.y;
            }
            if (ACT == 1) {
                v0 = 0.5f * v0 * (1.f + erff(v0 * 0.7071067811865475f));
                v1 = 0.5f * v1 * (1.f + erff(v1 * 0.7071067811865475f));
                v2 = 0.5f * v2 * (1.f + erff(v2 * 0.7071067811865475f));
                v3 = 0.5f * v3 * (1.f + erff(v3 * 0.7071067811865475f));
            }
            if (SPLITOUT) {
                bf16 h0, h1, h2, h3, l0, l1, l2, l3;
                split2(v0, h0, l0); split2(v1, h1, l1);
                split2(v2, h2, l2); split2(v3, h3, l3);
                *reinterpret_cast<__nv_bfloat162*>(Oh + (size_t)r_lo * Ndim + c) = __nv_bfloat162(h0, h1);
                *reinterpret_cast<__nv_bfloat162*>(Oh + (size_t)r_hi * Ndim + c) = __nv_bfloat162(h2, h3);
                *reinterpret_cast<__nv_bfloat162*>(Ol + (size_t)r_lo * Ndim + c) = __nv_bfloat162(l0, l1);
                *reinterpret_cast<__nv_bfloat162*>(Ol + (size_t)r_hi * Ndim + c) = __nv_bfloat162(l2, l3);
            } else {
                *reinterpret_cast<float2*>(C + (size_t)r_lo * Ndim + c) = make_float2(v0, v1);
                *reinterpret_cast<float2*>(C + (size_t)r_hi * Ndim + c) = make_float2(v2, v3);
            }
        }
    }
}

// ---------------------------------------------------------------------------
// Fused flash attention (per (b,h)): ctx = softmax(QK^T/8 + mask) @ V
// Q,K split bf16 [B*S][HID]; V^T split [B][HID][SEQ]; out split ctx [B,S,HID].
// CTA: 128 query rows, 8 warps x 16 rows; loop over 16 key blocks of 64.
// S stays in mma accumulators; online softmax; P accs map directly onto
// PV A-fragments. 3-term split on both GEMMs.
// ---------------------------------------------------------------------------
__global__ __launch_bounds__(256, 1)
void flash_attn(const bf16* __restrict__ qh, const bf16* __restrict__ ql,
                const bf16* __restrict__ kh, const bf16* __restrict__ kl,
                const bf16* __restrict__ vth, const bf16* __restrict__ vtl,
                const float* __restrict__ mask,
                bf16* __restrict__ ch, bf16* __restrict__ cl)
{
    __shared__ bf16 sKh[FBN][72], sKl[FBN][72];     // [key][d]
    __shared__ bf16 sVh[HDIM][72], sVl[HDIM][72];   // [d][key]
    __shared__ float sMask[SEQ];

    const int z = blockIdx.y;
    const int b = z / NHEAD, h = z % NHEAD;
    const int row0 = blockIdx.x * FBM;
    const int tid  = threadIdx.x;
    const int wid  = tid >> 5;
    const int lane = tid & 31;
    const int gg   = lane >> 2;
    const int tg   = lane & 3;
    const int mrow = row0 + wid * 16;   // warp's first query row
    const size_t hoff = (size_t)h * HDIM;

    // mask row for this batch into smem (once)
    for (int i = tid; i < SEQ; i += 256)
        sMask[i] = mask[(size_t)b * SEQ + i];

    // Q fragments (4 k-steps), loaded directly from gmem
    uint32_t qfh[4][4], qfl[4][4];
#pragma unroll
    for (int kk = 0; kk < 4; kk++) {
        const size_t r0 = ((size_t)(b * SEQ + mrow + gg))     * HID + hoff + kk * 16 + 2 * tg;
        const size_t r1 = ((size_t)(b * SEQ + mrow + 8 + gg)) * HID + hoff + kk * 16 + 2 * tg;
        qfh[kk][0] = *reinterpret_cast<const uint32_t*>(qh + r0);
        qfh[kk][1] = *reinterpret_cast<const uint32_t*>(qh + r1);
        qfh[kk][2] = *reinterpret_cast<const uint32_t*>(qh + r0 + 8);
        qfh[kk][3] = *reinterpret_cast<const uint32_t*>(qh + r1 + 8);
        qfl[kk][0] = *reinterpret_cast<const uint32_t*>(ql + r0);
        qfl[kk][1] = *reinterpret_cast<const uint32_t*>(ql + r1);
        qfl[kk][2] = *reinterpret_cast<const uint32_t*>(ql + r0 + 8);
        qfl[kk][3] = *reinterpret_cast<const uint32_t*>(ql + r1 + 8);
    }

    float o[8][4];
#pragma unroll
    for (int j = 0; j < 8; j++)
#pragma unroll
        for (int t = 0; t < 4; t++) o[j][t] = 0.f;
    float m0 = -1e30f, m1 = -1e30f, l0 = 0.f, l1 = 0.f;

    const int lrow = tid >> 2;        // 0..63
    const int lc   = (tid & 3) * 16;  // 0,16,32,48

    for (int k0 = 0; k0 < SEQ; k0 += FBN) {
        // stage K block [64 keys][64 d] and V^T block [64 d][64 keys]
        {
            const size_t gk = ((size_t)(b * SEQ + k0 + lrow)) * HID + hoff + lc;
            *reinterpret_cast<uint4*>(&sKh[lrow][lc])     = *reinterpret_cast<const uint4*>(kh + gk);
            *reinterpret_cast<uint4*>(&sKh[lrow][lc + 8]) = *reinterpret_cast<const uint4*>(kh + gk + 8);
            *reinterpret_cast<uint4*>(&sKl[lrow][lc])     = *reinterpret_cast<const uint4*>(kl + gk);
            *reinterpret_cast<uint4*>(&sKl[lrow][lc + 8]) = *reinterpret_cast<const uint4*>(kl + gk + 8);
            const size_t gv = ((size_t)b * HID + hoff + lrow) * SEQ + k0 + lc;
            *reinterpret_cast<uint4*>(&sVh[lrow][lc])     = *reinterpret_cast<const uint4*>(vth + gv);
            *reinterpret_cast<uint4*>(&sVh[lrow][lc + 8]) = *reinterpret_cast<const uint4*>(vth + gv + 8);
            *reinterpret_cast<uint4*>(&sVl[lrow][lc])     = *reinterpret_cast<const uint4*>(vtl + gv);
            *reinterpret_cast<uint4*>(&sVl[lrow][lc + 8]) = *reinterpret_cast<const uint4*>(vtl + gv + 8);
        }
        __syncthreads();

        // S = Q K^T  (8 n-tiles of 8 keys)
        float S[8][4];
#pragma unroll
        for (int j = 0; j < 8; j++)
#pragma unroll
            for (int t = 0; t < 4; t++) S[j][t] = 0.f;

#pragma unroll
        for (int kk = 0; kk < 4; kk++) {
#pragma unroll
            for (int j = 0; j < 8; j++) {
                uint32_t bh[2], bl[2];
                bh[0] = *reinterpret_cast<const uint32_t*>(&sKh[j * 8 + gg][kk * 16 + 2 * tg]);
                bh[1] = *reinterpret_cast<const uint32_t*>(&sKh[j * 8 + gg][kk * 16 + 2 * tg + 8]);
                bl[0] = *reinterpret_cast<const uint32_t*>(&sKl[j * 8 + gg][kk * 16 + 2 * tg]);
                bl[1] = *reinterpret_cast<const uint32_t*>(&sKl[j * 8 + gg][kk * 16 + 2 * tg + 8]);
                mma16816(S[j], qfh[kk], bh);
                mma16816(S[j], qfh[kk], bl);
                mma16816(S[j], qfl[kk], bh);
            }
        }

        // scale + additive mask
#pragma unroll
        for (int j = 0; j < 8; j++) {
            const float mk0 = sMask[k0 + j * 8 + 2 * tg];
            const float mk1 = sMask[k0 + j * 8 + 2 * tg + 1];
            S[j][0] = S[j][0] * 0.125f + mk0;
            S[j][1] = S[j][1] * 0.125f + mk1;
            S[j][2] = S[j][2] * 0.125f + mk0;
            S[j][3] = S[j][3] * 0.125f + mk1;
        }

        // online softmax (rows gg, gg+8 per thread; quad holds full row)
        float mx0 = -1e30f, mx1 = -1e30f;
#pragma unroll
        for (int j = 0; j < 8; j++) {
            mx0 = fmaxf(mx0, fmaxf(S[j][0], S[j][1]));
            mx1 = fmaxf(mx1, fmaxf(S[j][2], S[j][3]));
        }
        mx0 = fmaxf(mx0, __shfl_xor_sync(0xffffffffu, mx0, 1));
        mx0 = fmaxf(mx0, __shfl_xor_sync(0xffffffffu, mx0, 2));
        mx1 = fmaxf(mx1, __shfl_xor_sync(0xffffffffu, mx1, 1));
        mx1 = fmaxf(mx1, __shfl_xor_sync(0xffffffffu, mx1, 2));

        const float mn0 = fmaxf(m0, mx0);
        const float mn1 = fmaxf(m1, mx1);
        const float a0 = __expf(m0 - mn0);
        const float a1 = __expf(m1 - mn1);
        m0 = mn0; m1 = mn1;

        float s0 = 0.f, s1 = 0.f;
#pragma unroll
        for (int j = 0; j < 8; j++) {
            S[j][0] = __expf(S[j][0] - m0); s0 += S[j][0];
            S[j][1] = __expf(S[j][1] - m0); s0 += S[j][1];
            S[j][2] = __expf(S[j][2] - m1); s1 += S[j][2];
            S[j][3] = __expf(S[j][3] - m1); s1 += S[j][3];
        }
        s0 += __shfl_xor_sync(0xffffffffu, s0, 1);
        s0 += __shfl_xor_sync(0xffffffffu, s0, 2);
        s1 += __shfl_xor_sync(0xffffffffu, s1, 1);
        s1 += __shfl_xor_sync(0xffffffffu, s1, 2);
        l0 = l0 * a0 + s0;
        l1 = l1 * a1 + s1;

        // rescale O
#pragma unroll
        for (int j = 0; j < 8; j++) {
            o[j][0] *= a0; o[j][1] *= a0;
            o[j][2] *= a1; o[j][3] *= a1;
        }

        // P accumulators -> A fragments (tiles 2kk, 2kk+1), split bf16
        uint32_t pfh[4][4], pfl[4][4];
#pragma unroll
        for (int kk = 0; kk < 4; kk++) {
            bf16 h0, h1, lo0, lo1;
            split2(S[2 * kk][0], h0, lo0); split2(S[2 * kk][1], h1, lo1);
            pfh[kk][0] = pack_bf2(h0, h1); pfl[kk][0] = pack_bf2(lo0, lo1);
            split2(S[2 * kk][2], h0, lo0); split2(S[2 * kk][3], h1, lo1);
            pfh[kk][1] = pack_bf2(h0, h1); pfl[kk][1] = pack_bf2(lo0, lo1);
            split2(S[2 * kk + 1][0], h0, lo0); split2(S[2 * kk + 1][1], h1, lo1);
            pfh[kk][2] = pack_bf2(h0, h1); pfl[kk][2] = pack_bf2(lo0, lo1);
            split2(S[2 * kk + 1][2], h0, lo0); split2(S[2 * kk + 1][3], h1, lo1);
            pfh[kk][3] = pack_bf2(h0, h1); pfl[kk][3] = pack_bf2(lo0, lo1);
        }

        // O += P V
#pragma unroll
        for (int kk = 0; kk < 4; kk++) {
#pragma unroll
            for (int jd = 0; jd < 8; jd++) {
                uint32_t bh[2], bl[2];
                bh[0] = *reinterpret_cast<const uint32_t*>(&sVh[jd * 8 + gg][kk * 16 + 2 * tg]);
                bh[1] = *reinterpret_cast<const uint32_t*>(&sVh[jd * 8 + gg][kk * 16 + 2 * tg + 8]);
                bl[0] = *reinterpret_cast<const uint32_t*>(&sVl[jd * 8 + gg][kk * 16 + 2 * tg]);
                bl[1] = *reinterpret_cast<const uint32_t*>(&sVl[jd * 8 + gg][kk * 16 + 2 * tg + 8]);
                mma16816(o[jd], pfh[kk], bh);
                mma16816(o[jd], pfh[kk], bl);
                mma16816(o[jd], pfl[kk], bh);
            }
        }
        __syncthreads();
    }

    // epilogue: normalize, split-store ctx
    const float inv0 = 1.f / l0;
    const float inv1 = 1.f / l1;
    const size_t r_lo = (size_t)(b * SEQ) + mrow + gg;
    const size_t r_hi = r_lo + 8;
#pragma unroll
    for (int jd = 0; jd < 8; jd++) {
        const size_t c = hoff + jd * 8 + 2 * tg;
        float v0 = o[jd][0] * inv0, v1 = o[jd][1] * inv0;
        float v2 = o[jd][2] * inv1, v3 = o[jd][3] * inv1;
        bf16 h0, h1, h2, h3, lo0, lo1, lo2, lo3;
        split2(v0, h0, lo0); split2(v1, h1, lo1);
        split2(v2, h2, lo2); split2(v3, h3, lo3);
        *reinterpret_cast<__nv_bfloat162*>(ch + r_lo * HID + c) = __nv_bfloat162(h0, h1);
        *reinterpret_cast<__nv_bfloat162*>(ch + r_hi * HID + c) = __nv_bfloat162(h2, h3);
        *reinterpret_cast<__nv_bfloat162*>(cl + r_lo * HID + c) = __nv_bfloat162(lo0, lo1);
        *reinterpret_cast<__nv_bfloat162*>(cl + r_hi * HID + c) = __nv_bfloat162(lo2, lo3);
    }
}

// ---------------------------------------------------------------------------
// LayerNorm over HID=768, bf16 split outputs fused.
// ---------------------------------------------------------------------------
__global__ __launch_bounds__(256)
void layernorm_split(const float* __restrict__ x, const float* __restrict__ gam,
                     const float* __restrict__ bet, float* __restrict__ out,
                     bf16* __restrict__ oh, bf16* __restrict__ ol)
{
    const int row = blockIdx.x;
    const float* xr = x + (size_t)row * HID;
    const int tid = threadIdx.x;
    __shared__ float rs_[8], rq_[8];

    float v0 = xr[tid], v1 = xr[tid + 256], v2 = xr[tid + 512];
    float s  = v0 + v1 + v2;
    float sq = v0 * v0 + v1 * v1 + v2 * v2;
#pragma unroll
    for (int o = 16; o; o >>= 1) {
        s  += __shfl_xor_sync(0xffffffffu, s,  o);
        sq += __shfl_xor_sync(0xffffffffu, sq, o);
    }
    if ((tid & 31) == 0) { rs_[tid >> 5] = s; rq_[tid >> 5] = sq; }
    __syncthreads();
    float ts = 0.f, tq = 0.f;
#pragma unroll
    for (int i = 0; i < 8; i++) { ts += rs_[i]; tq += rq_[i]; }
    const float mean = ts * (1.f / HID);
    const float var  = tq * (1.f / HID) - mean * mean;
    const float rstd = rsqrtf(var + 1e-5f);

    float* o = out + (size_t)row * HID;
    float r0 = (v0 - mean) * rstd * gam[tid]       + bet[tid];
    float r1 = (v1 - mean) * rstd * gam[tid + 256] + bet[tid + 256];
    float r2 = (v2 - mean) * rstd * gam[tid + 512] + bet[tid + 512];
    o[tid] = r0; o[tid + 256] = r1; o[tid + 512] = r2;

    bf16 h, l;
    split2(r0, h, l); oh[(size_t)row * HID + tid]       = h; ol[(size_t)row * HID + tid]       = l;
    split2(r1, h, l); oh[(size_t)row * HID + tid + 256] = h; ol[(size_t)row * HID + tid + 256] = l;
    split2(r2, h, l); oh[(size_t)row * HID + tid + 512] = h; ol[(size_t)row * HID + tid + 512] = l;
}

// ---------------------------------------------------------------------------
// Launcher
// ---------------------------------------------------------------------------
extern "C" void kernel_launch(void* const* d_in, const int* in_sizes, int n_in,
                              void* d_out, int out_size)
{
    (void)in_sizes; (void)n_in; (void)out_size;
    const float* hs    = (const float*)d_in[0];
    const float* mask  = (const float*)d_in[1];
    const float* q_w   = (const float*)d_in[2];
    const float* q_b   = (const float*)d_in[3];
    const float* k_w   = (const float*)d_in[4];
    const float* k_b   = (const float*)d_in[5];
    const float* v_w   = (const float*)d_in[6];
    const float* v_b   = (const float*)d_in[7];
    const float* ao_w  = (const float*)d_in[8];
    const float* ao_b  = (const float*)d_in[9];
    const float* ln1_g = (const float*)d_in[10];
    const float* ln1_b = (const float*)d_in[11];
    const float* ff1_w = (const float*)d_in[12];
    const float* ff1_b = (const float*)d_in[13];
    const float* ff2_w = (const float*)d_in[14];
    const float* ff2_b = (const float*)d_in[15];
    const float* ln2_g = (const float*)d_in[16];
    const float* ln2_b = (const float*)d_in[17];
    float* out = (float*)d_out;

    float *x, *v, *y, *attn, *y2;
    cudaGetSymbolAddress((void**)&x,    g_x);
    cudaGetSymbolAddress((void**)&v,    g_v);
    cudaGetSymbolAddress((void**)&y,    g_y);
    cudaGetSymbolAddress((void**)&attn, g_attn);
    cudaGetSymbolAddress((void**)&y2,   g_y2);

    bf16 *xh,*xl,*qh,*ql,*kh,*kl,*vth,*vtl,*ch,*cl,*ah,*al,*fh,*fl;
    cudaGetSymbolAddress((void**)&xh,  g_xh);  cudaGetSymbolAddress((void**)&xl,  g_xl);
    cudaGetSymbolAddress((void**)&qh,  g_qh);  cudaGetSymbolAddress((void**)&ql,  g_ql);
    cudaGetSymbolAddress((void**)&kh,  g_kh);  cudaGetSymbolAddress((void**)&kl,  g_kl);
    cudaGetSymbolAddress((void**)&vth, g_vth); cudaGetSymbolAddress((void**)&vtl, g_vtl);
    cudaGetSymbolAddress((void**)&ch,  g_ch);  cudaGetSymbolAddress((void**)&cl,  g_cl);
    cudaGetSymbolAddress((void**)&ah,  g_ah);  cudaGetSymbolAddress((void**)&al,  g_al);
    cudaGetSymbolAddress((void**)&fh,  g_fh);  cudaGetSymbolAddress((void**)&fl,  g_fl);

    bf16 *qwh,*qwl,*kwh,*kwl,*vwh,*vwl,*awh,*awl,*f1h,*f1l,*f2h,*f2l;
    cudaGetSymbolAddress((void**)&qwh, g_qwh); cudaGetSymbolAddress((void**)&qwl, g_qwl);
    cudaGetSymbolAddress((void**)&kwh, g_kwh); cudaGetSymbolAddress((void**)&kwl, g_kwl);
    cudaGetSymbolAddress((void**)&vwh, g_vwh); cudaGetSymbolAddress((void**)&vwl, g_vwl);
    cudaGetSymbolAddress((void**)&awh, g_awh); cudaGetSymbolAddress((void**)&awl, g_awl);
    cudaGetSymbolAddress((void**)&f1h, g_f1h); cudaGetSymbolAddress((void**)&f1l, g_f1l);
    cudaGetSymbolAddress((void**)&f2h, g_f2h); cudaGetSymbolAddress((void**)&f2l, g_f2l);

    const int nHH = HID * HID, nHF = HID * FFDIM;
    split_wT<<<(nHH + 255) / 256, 256>>>(q_w,  qwh, qwl, HID, HID);
    split_wT<<<(nHH + 255) / 256, 256>>>(k_w,  kwh, kwl, HID, HID);
    split_wT<<<(nHH + 255) / 256, 256>>>(v_w,  vwh, vwl, HID, HID);
    split_wT<<<(nHH + 255) / 256, 256>>>(ao_w, awh, awl, HID, HID);
    split_wT<<<(nHF + 255) / 256, 256>>>(ff1_w, f1h, f1l, HID, FFDIM);
    split_wT<<<(nHF + 255) / 256, 256>>>(ff2_w, f2h, f2l, FFDIM, HID);

    const dim3 gH (HID   / 128, MTOK / 128);
    const dim3 gFF(FFDIM / 128, MTOK / 128);
    const dim3 gFA(SEQ / FBM, NBH);
    const dim3 gVT(SEQ / 32, HID / 32, BATCH);
    const int nACT = MTOK * HID;

    split_act<<<(nACT / 4 + 255) / 256, 256>>>(hs, xh, xl, nACT);

    for (int l = 0; l < L_LAYERS; l++) {
        const float* xin = (l == 0) ? hs : x;

        tc_gemm<0, false, true><<<gH, 256>>>(xh, xl, qwh, qwl, q_b, nullptr,
                                             nullptr, qh, ql, HID, HID);
        tc_gemm<0, false, true><<<gH, 256>>>(xh, xl, kwh, kwl, k_b, nullptr,
                                             nullptr, kh, kl, HID, HID);
        tc_gemm<0, false, false><<<gH, 256>>>(xh, xl, vwh, vwl, v_b, nullptr,
                                              v, nullptr, nullptr, HID, HID);
        split_vT<<<gVT, dim3(32, 8)>>>(v, vth, vtl);

        flash_attn<<<gFA, 256>>>(qh, ql, kh, kl, vth, vtl, mask, ch, cl);

        tc_gemm<0, true, false><<<gH, 256>>>(ch, cl, awh, awl, ao_b, xin,
                                             y, nullptr, nullptr, HID, HID);
        layernorm_split<<<MTOK, 256>>>(y, ln1_g, ln1_b, attn, ah, al);

        tc_gemm<1, false, true><<<gFF, 256>>>(ah, al, f1h, f1l, ff1_b, nullptr,
                                              nullptr, fh, fl, FFDIM, HID);
        tc_gemm<0, true, false><<<gH, 256>>>(fh, fl, f2h, f2l, ff2_b, attn,
                                             y2, nullptr, nullptr, HID, FFDIM);

        float* xo = (l == L_LAYERS - 1) ? out : x;
        layernorm_split<<<MTOK, 256>>>(y2, ln2_g, ln2_b, xo, xh, xl);
    }
}

// round 13
// speedup vs baseline: 1.3220x; 1.0845x over previous
#include <cuda_runtime.h>
#include <cuda_bf16.h>
#include <math.h>
#include <stdint.h>

#define L_LAYERS 6
#define BATCH    4
#define SEQ      1024
#define HID      768
#define NHEAD    12
#define HDIM     64
#define FFDIM    3072
#define MTOK     (BATCH*SEQ)      // 4096 tokens
#define NBH      (BATCH*NHEAD)    // 48
#define FBM      128              // flash: query rows per CTA
#define FBN      64               // flash: keys per iteration
#define QKVD     2304             // fused QKV output width

typedef __nv_bfloat16 bf16;

// ---------------------------------------------------------------------------
// Scratch (device globals)
// ---------------------------------------------------------------------------
__device__ float g_x   [MTOK*HID];
__device__ float g_y   [MTOK*HID];
__device__ float g_attn[MTOK*HID];
__device__ float g_y2  [MTOK*HID];

__device__ bf16 g_xh[MTOK*HID],   g_xl[MTOK*HID];
__device__ bf16 g_qkvh[MTOK*QKVD],g_qkvl[MTOK*QKVD]; // fused QKV split
__device__ bf16 g_vth[MTOK*HID],  g_vtl[MTOK*HID];   // V^T per batch [HID][SEQ]
__device__ bf16 g_ch[MTOK*HID],   g_cl[MTOK*HID];    // ctx split
__device__ bf16 g_ah[MTOK*HID],   g_al[MTOK*HID];    // LN1 split
__device__ bf16 g_fh[MTOK*FFDIM], g_fl[MTOK*FFDIM];  // FF hidden split

// weights split, transposed [N,K]
__device__ bf16  g_qkvwh[QKVD*HID], g_qkvwl[QKVD*HID];
__device__ float g_qkvb[QKVD];
__device__ bf16  g_awh[HID*HID],   g_awl[HID*HID];
__device__ bf16  g_f1h[HID*FFDIM], g_f1l[HID*FFDIM];
__device__ bf16  g_f2h[FFDIM*HID], g_f2l[FFDIM*HID];

__device__ __forceinline__ void split2(float v, bf16& h, bf16& l)
{
    h = __float2bfloat16_rn(v);
    l = __float2bfloat16_rn(v - __bfloat162float(h));
}

__device__ __forceinline__ uint32_t pack_bf2(bf16 a, bf16 b)
{
    __nv_bfloat162 t(a, b);
    return *reinterpret_cast<uint32_t*>(&t);
}

// ---------------------------------------------------------------------------
// Split helpers
// ---------------------------------------------------------------------------
__global__ __launch_bounds__(256)
void split_act(const float* __restrict__ x, bf16* __restrict__ h,
               bf16* __restrict__ l, int n)
{
    int i = (blockIdx.x * 256 + threadIdx.x) * 4;
    if (i >= n) return;
    float4 v = *reinterpret_cast<const float4*>(x + i);
    bf16 h0, h1, h2, h3, l0, l1, l2, l3;
    split2(v.x, h0, l0); split2(v.y, h1, l1);
    split2(v.z, h2, l2); split2(v.w, h3, l3);
    __nv_bfloat162* hp = reinterpret_cast<__nv_bfloat162*>(h + i);
    __nv_bfloat162* lp = reinterpret_cast<__nv_bfloat162*>(l + i);
    hp[0] = __nv_bfloat162(h0, h1); hp[1] = __nv_bfloat162(h2, h3);
    lp[0] = __nv_bfloat162(l0, l1); lp[1] = __nv_bfloat162(l2, l3);
}

// W[K,N] row-major -> split, transposed to [N,K]
__global__ __launch_bounds__(256)
void split_wT(const float* __restrict__ W, bf16* __restrict__ hT,
              bf16* __restrict__ lT, int K, int N)
{
    int idx = blockIdx.x * 256 + threadIdx.x;
    if (idx >= K * N) return;
    int k = idx / N, n = idx - k * N;
    bf16 h, l;
    split2(W[idx], h, l);
    hT[(size_t)n * K + k] = h;
    lT[(size_t)n * K + k] = l;
}

// q/k/v weights [768,768] -> combined transposed [2304][768] + combined bias
__global__ __launch_bounds__(256)
void split_wT3(const float* __restrict__ Wq, const float* __restrict__ Wk,
               const float* __restrict__ Wv,
               const float* __restrict__ bq, const float* __restrict__ bk,
               const float* __restrict__ bv,
               bf16* __restrict__ hT, bf16* __restrict__ lT,
               float* __restrict__ bias)
{
    int idx = blockIdx.x * 256 + threadIdx.x;
    if (idx < QKVD) {
        bias[idx] = (idx < HID) ? bq[idx]
                  : (idx < 2 * HID) ? bk[idx - HID] : bv[idx - 2 * HID];
    }
    if (idx >= HID * HID) return;
    int k = idx / HID, n = idx - k * HID;
    bf16 h, l;
    split2(Wq[idx], h, l);
    hT[(size_t)n * HID + k] = h;               lT[(size_t)n * HID + k] = l;
    split2(Wk[idx], h, l);
    hT[(size_t)(n + HID) * HID + k] = h;       lT[(size_t)(n + HID) * HID + k] = l;
    split2(Wv[idx], h, l);
    hT[(size_t)(n + 2 * HID) * HID + k] = h;   lT[(size_t)(n + 2 * HID) * HID + k] = l;
}

// transpose split V from qkv buffer (cols [1536,2304)) -> [B][HID][SEQ]
__global__ __launch_bounds__(256)
void trans_v(const bf16* __restrict__ qkvh, const bf16* __restrict__ qkvl,
             bf16* __restrict__ th, bf16* __restrict__ tl)
{
    __shared__ bf16 t0[32][33];
    __shared__ bf16 t1[32][33];
    const int b  = blockIdx.z;
    const int s0 = blockIdx.x * 32;
    const int d0 = blockIdx.y * 32;
    const int x  = threadIdx.x;     // 0..31
    const int y  = threadIdx.y;     // 0..7
#pragma unroll
    for (int i = 0; i < 32; i += 8) {
        size_t g = ((size_t)b * SEQ + s0 + y + i) * QKVD + 2 * HID + d0 + x;
        t0[y + i][x] = qkvh[g];
        t1[y + i][x] = qkvl[g];
    }
    __syncthreads();
#pragma unroll
    for (int i = 0; i < 32; i += 8) {
        size_t o = ((size_t)b * HID + d0 + y + i) * SEQ + s0 + x;
        th[o] = t0[x][y + i];
        tl[o] = t1[x][y + i];
    }
}

// ---------------------------------------------------------------------------
// mma.sync m16n8k16 bf16 -> fp32
// ---------------------------------------------------------------------------
__device__ __forceinline__ void mma16816(float* c, const uint32_t* a, const uint32_t* b)
{
    asm("mma.sync.aligned.m16n8k16.row.col.f32.bf16.bf16.f32 "
        "{%0,%1,%2,%3}, {%4,%5,%6,%7}, {%8,%9}, {%0,%1,%2,%3};"
        : "+f"(c[0]), "+f"(c[1]), "+f"(c[2]), "+f"(c[3])
        : "r"(a[0]), "r"(a[1]), "r"(a[2]), "r"(a[3]), "r"(b[0]), "r"(b[1]));
}

// ---------------------------------------------------------------------------
// Dense tensor-core GEMM (3-term split): C = A@W + bias (+res)(+GELU)
// A:[M,K] split pair, W:[N,K] split pair. BM=BN=128, BK=16, 8 warps (2x4).
// SPLITOUT: write bf16 (h,l) pair instead of fp32.
// ---------------------------------------------------------------------------
template<int ACT, bool HASRES, bool SPLITOUT>
__global__ __launch_bounds__(256, 1)
void tc_gemm(const bf16* __restrict__ Ah, const bf16* __restrict__ Al,
             const bf16* __restrict__ WhT, const bf16* __restrict__ WlT,
             const float* __restrict__ bias, const float* __restrict__ res,
             float* __restrict__ C, bf16* __restrict__ Oh, bf16* __restrict__ Ol,
             int Ndim, int Kdim)
{
    __shared__ bf16 sAh[2][128][24];
    __shared__ bf16 sAl[2][128][24];
    __shared__ bf16 sBh[2][128][24];
    __shared__ bf16 sBl[2][128][24];

    const int tid  = threadIdx.x;
    const int row0 = blockIdx.y * 128;
    const int col0 = blockIdx.x * 128;
    const int lrow = tid >> 1;
    const int kofs = (tid & 1) * 8;

    const bf16* pAh = Ah  + (size_t)(row0 + lrow) * Kdim + kofs;
    const bf16* pAl = Al  + (size_t)(row0 + lrow) * Kdim + kofs;
    const bf16* pBh = WhT + (size_t)(col0 + lrow) * Kdim + kofs;
    const bf16* pBl = WlT + (size_t)(col0 + lrow) * Kdim + kofs;

    const int wid  = tid >> 5;
    const int m0   = (wid & 1) * 64;
    const int n0   = (wid >> 1) * 32;
    const int lane = tid & 31;
    const int gg   = lane >> 2;
    const int tg   = lane & 3;

    float acc[4][4][4];
#pragma unroll
    for (int i = 0; i < 4; i++)
#pragma unroll
        for (int j = 0; j < 4; j++)
#pragma unroll
            for (int t = 0; t < 4; t++) acc[i][j][t] = 0.f;

    {
        uint4 a_h = *reinterpret_cast<const uint4*>(pAh);
        uint4 a_l = *reinterpret_cast<const uint4*>(pAl);
        uint4 b_h = *reinterpret_cast<const uint4*>(pBh);
        uint4 b_l = *reinterpret_cast<const uint4*>(pBl);
        *reinterpret_cast<uint4*>(&sAh[0][lrow][kofs]) = a_h;
        *reinterpret_cast<uint4*>(&sAl[0][lrow][kofs]) = a_l;
        *reinterpret_cast<uint4*>(&sBh[0][lrow][kofs]) = b_h;
        *reinterpret_cast<uint4*>(&sBl[0][lrow][kofs]) = b_l;
    }
    __syncthreads();

    int s = 0;
    for (int k0 = 0; k0 < Kdim; k0 += 16) {
        const bool has_next = (k0 + 16 < Kdim);
        uint4 nAh, nAl, nBh, nBl;
        if (has_next) {
            nAh = *reinterpret_cast<const uint4*>(pAh + k0 + 16);
            nAl = *reinterpret_cast<const uint4*>(pAl + k0 + 16);
            nBh = *reinterpret_cast<const uint4*>(pBh + k0 + 16);
            nBl = *reinterpret_cast<const uint4*>(pBl + k0 + 16);
        }

        uint32_t afh[4][4], afl[4][4], bfh[4][2], bfl[4][2];
#pragma unroll
        for (int i = 0; i < 4; i++) {
            const int r = m0 + i * 16;
            afh[i][0] = *reinterpret_cast<const uint32_t*>(&sAh[s][r + gg    ][2 * tg    ]);
            afh[i][1] = *reinterpret_cast<const uint32_t*>(&sAh[s][r + 8 + gg][2 * tg    ]);
            afh[i][2] = *reinterpret_cast<const uint32_t*>(&sAh[s][r + gg    ][2 * tg + 8]);
            afh[i][3] = *reinterpret_cast<const uint32_t*>(&sAh[s][r + 8 + gg][2 * tg + 8]);
            afl[i][0] = *reinterpret_cast<const uint32_t*>(&sAl[s][r + gg    ][2 * tg    ]);
            afl[i][1] = *reinterpret_cast<const uint32_t*>(&sAl[s][r + 8 + gg][2 * tg    ]);
            afl[i][2] = *reinterpret_cast<const uint32_t*>(&sAl[s][r + gg    ][2 * tg + 8]);
            afl[i][3] = *reinterpret_cast<const uint32_t*>(&sAl[s][r + 8 + gg][2 * tg + 8]);
        }
#pragma unroll
        for (int j = 0; j < 4; j++) {
            const int c = n0 + j * 8;
            bfh[j][0] = *reinterpret_cast<const uint32_t*>(&sBh[s][c + gg][2 * tg    ]);
            bfh[j][1] = *reinterpret_cast<const uint32_t*>(&sBh[s][c + gg][2 * tg + 8]);
            bfl[j][0] = *reinterpret_cast<const uint32_t*>(&sBl[s][c + gg][2 * tg    ]);
            bfl[j][1] = *reinterpret_cast<const uint32_t*>(&sBl[s][c + gg][2 * tg + 8]);
        }

#pragma unroll
        for (int i = 0; i < 4; i++)
#pragma unroll
            for (int j = 0; j < 4; j++) {
                mma16816(acc[i][j], afh[i], bfh[j]);
                mma16816(acc[i][j], afh[i], bfl[j]);
                mma16816(acc[i][j], afl[i], bfh[j]);
            }

        if (has_next) {
            const int ns = s ^ 1;
            *reinterpret_cast<uint4*>(&sAh[ns][lrow][kofs]) = nAh;
            *reinterpret_cast<uint4*>(&sAl[ns][lrow][kofs]) = nAl;
            *reinterpret_cast<uint4*>(&sBh[ns][lrow][kofs]) = nBh;
            *reinterpret_cast<uint4*>(&sBl[ns][lrow][kofs]) = nBl;
            __syncthreads();
        }
        s ^= 1;
    }

#pragma unroll
    for (int i = 0; i < 4; i++) {
        const int r_lo = row0 + m0 + i * 16 + gg;
        const int r_hi = r_lo + 8;
#pragma unroll
        for (int j = 0; j < 4; j++) {
            const int c = col0 + n0 + j * 8 + 2 * tg;
            float2 b2 = *reinterpret_cast<const float2*>(bias + c);
            float v0 = acc[i][j][0] + b2.x;
            float v1 = acc[i][j][1] + b2.y;
            float v2 = acc[i][j][2] + b2.x;
            float v3 = acc[i][j][3] + b2.y;
            if (HASRES) {
                float2 r0 = *reinterpret_cast<const float2*>(res + (size_t)r_lo * Ndim + c);
                float2 r1 = *reinterpret_cast<const float2*>(res + (size_t)r_hi * Ndim + c);
                v0 += r0.x; v1 += r0.y; v2 += r1.x; v3 += r1.y;
            }
            if (ACT == 1) {
                v0 = 0.5f * v0 * (1.f + erff(v0 * 0.7071067811865475f));
                v1 = 0.5f * v1 * (1.f + erff(v1 * 0.7071067811865475f));
                v2 = 0.5f * v2 * (1.f + erff(v2 * 0.7071067811865475f));
                v3 = 0.5f * v3 * (1.f + erff(v3 * 0.7071067811865475f));
            }
            if (SPLITOUT) {
                bf16 h0, h1, h2, h3, l0, l1, l2, l3;
                split2(v0, h0, l0); split2(v1, h1, l1);
                split2(v2, h2, l2); split2(v3, h3, l3);
                *reinterpret_cast<__nv_bfloat162*>(Oh + (size_t)r_lo * Ndim + c) = __nv_bfloat162(h0, h1);
                *reinterpret_cast<__nv_bfloat162*>(Oh + (size_t)r_hi * Ndim + c) = __nv_bfloat162(h2, h3);
                *reinterpret_cast<__nv_bfloat162*>(Ol + (size_t)r_lo * Ndim + c) = __nv_bfloat162(l0, l1);
                *reinterpret_cast<__nv_bfloat162*>(Ol + (size_t)r_hi * Ndim + c) = __nv_bfloat162(l2, l3);
            } else {
                *reinterpret_cast<float2*>(C + (size_t)r_lo * Ndim + c) = make_float2(v0, v1);
                *reinterpret_cast<float2*>(C + (size_t)r_hi * Ndim + c) = make_float2(v2, v3);
            }
        }
    }
}

// ---------------------------------------------------------------------------
// Fused flash attention (per (b,h)): ctx = softmax(QK^T/8 + mask) @ V
// Q,K live in the fused qkv buffer [B*S][QKVD] (Q at col h*64, K at 768+h*64);
// V^T split [B][HID][SEQ]; out split ctx [B,S,HID].
// ---------------------------------------------------------------------------
__global__ __launch_bounds__(256, 1)
void flash_attn(const bf16* __restrict__ qkvh, const bf16* __restrict__ qkvl,
                const bf16* __restrict__ vth, const bf16* __restrict__ vtl,
                const float* __restrict__ mask,
                bf16* __restrict__ ch, bf16* __restrict__ cl)
{
    __shared__ bf16 sKh[FBN][72], sKl[FBN][72];     // [key][d]
    __shared__ bf16 sVh[HDIM][72], sVl[HDIM][72];   // [d][key]
    __shared__ float sMask[SEQ];

    const int z = blockIdx.y;
    const int b = z / NHEAD, h = z % NHEAD;
    const int row0 = blockIdx.x * FBM;
    const int tid  = threadIdx.x;
    const int wid  = tid >> 5;
    const int lane = tid & 31;
    const int gg   = lane >> 2;
    const int tg   = lane & 3;
    const int mrow = row0 + wid * 16;   // warp's first query row
    const size_t hoff = (size_t)h * HDIM;

    for (int i = tid; i < SEQ; i += 256)
        sMask[i] = mask[(size_t)b * SEQ + i];

    // Q fragments (4 k-steps), loaded directly from gmem
    uint32_t qfh[4][4], qfl[4][4];
#pragma unroll
    for (int kk = 0; kk < 4; kk++) {
        const size_t r0 = ((size_t)(b * SEQ + mrow + gg))     * QKVD + hoff + kk * 16 + 2 * tg;
        const size_t r1 = ((size_t)(b * SEQ + mrow + 8 + gg)) * QKVD + hoff + kk * 16 + 2 * tg;
        qfh[kk][0] = *reinterpret_cast<const uint32_t*>(qkvh + r0);
        qfh[kk][1] = *reinterpret_cast<const uint32_t*>(qkvh + r1);
        qfh[kk][2] = *reinterpret_cast<const uint32_t*>(qkvh + r0 + 8);
        qfh[kk][3] = *reinterpret_cast<const uint32_t*>(qkvh + r1 + 8);
        qfl[kk][0] = *reinterpret_cast<const uint32_t*>(qkvl + r0);
        qfl[kk][1] = *reinterpret_cast<const uint32_t*>(qkvl + r1);
        qfl[kk][2] = *reinterpret_cast<const uint32_t*>(qkvl + r0 + 8);
        qfl[kk][3] = *reinterpret_cast<const uint32_t*>(qkvl + r1 + 8);
    }

    float o[8][4];
#pragma unroll
    for (int j = 0; j < 8; j++)
#pragma unroll
        for (int t = 0; t < 4; t++) o[j][t] = 0.f;
    float m0 = -1e30f, m1 = -1e30f, l0 = 0.f, l1 = 0.f;

    const int lrow = tid >> 2;        // 0..63
    const int lc   = (tid & 3) * 16;  // 0,16,32,48

    for (int k0 = 0; k0 < SEQ; k0 += FBN) {
        // stage K block (from qkv cols 768+h*64) and V^T block
        {
            const size_t gk = ((size_t)(b * SEQ + k0 + lrow)) * QKVD + HID + hoff + lc;
            *reinterpret_cast<uint4*>(&sKh[lrow][lc])     = *reinterpret_cast<const uint4*>(qkvh + gk);
            *reinterpret_cast<uint4*>(&sKh[lrow][lc + 8]) = *reinterpret_cast<const uint4*>(qkvh + gk + 8);
            *reinterpret_cast<uint4*>(&sKl[lrow][lc])     = *reinterpret_cast<const uint4*>(qkvl + gk);
            *reinterpret_cast<uint4*>(&sKl[lrow][lc + 8]) = *reinterpret_cast<const uint4*>(qkvl + gk + 8);
            const size_t gv = ((size_t)b * HID + hoff + lrow) * SEQ + k0 + lc;
            *reinterpret_cast<uint4*>(&sVh[lrow][lc])     = *reinterpret_cast<const uint4*>(vth + gv);
            *reinterpret_cast<uint4*>(&sVh[lrow][lc + 8]) = *reinterpret_cast<const uint4*>(vth + gv + 8);
            *reinterpret_cast<uint4*>(&sVl[lrow][lc])     = *reinterpret_cast<const uint4*>(vtl + gv);
            *reinterpret_cast<uint4*>(&sVl[lrow][lc + 8]) = *reinterpret_cast<const uint4*>(vtl + gv + 8);
        }
        __syncthreads();

        // S = Q K^T
        float S[8][4];
#pragma unroll
        for (int j = 0; j < 8; j++)
#pragma unroll
            for (int t = 0; t < 4; t++) S[j][t] = 0.f;

#pragma unroll
        for (int kk = 0; kk < 4; kk++) {
#pragma unroll
            for (int j = 0; j < 8; j++) {
                uint32_t bh[2], bl[2];
                bh[0] = *reinterpret_cast<const uint32_t*>(&sKh[j * 8 + gg][kk * 16 + 2 * tg]);
                bh[1] = *reinterpret_cast<const uint32_t*>(&sKh[j * 8 + gg][kk * 16 + 2 * tg + 8]);
                bl[0] = *reinterpret_cast<const uint32_t*>(&sKl[j * 8 + gg][kk * 16 + 2 * tg]);
                bl[1] = *reinterpret_cast<const uint32_t*>(&sKl[j * 8 + gg][kk * 16 + 2 * tg + 8]);
                mma16816(S[j], qfh[kk], bh);
                mma16816(S[j], qfh[kk], bl);
                mma16816(S[j], qfl[kk], bh);
            }
        }

        // scale + additive mask
#pragma unroll
        for (int j = 0; j < 8; j++) {
            const float mk0 = sMask[k0 + j * 8 + 2 * tg];
            const float mk1 = sMask[k0 + j * 8 + 2 * tg + 1];
            S[j][0] = S[j][0] * 0.125f + mk0;
            S[j][1] = S[j][1] * 0.125f + mk1;
            S[j][2] = S[j][2] * 0.125f + mk0;
            S[j][3] = S[j][3] * 0.125f + mk1;
        }

        // online softmax
        float mx0 = -1e30f, mx1 = -1e30f;
#pragma unroll
        for (int j = 0; j < 8; j++) {
            mx0 = fmaxf(mx0, fmaxf(S[j][0], S[j][1]));
            mx1 = fmaxf(mx1, fmaxf(S[j][2], S[j][3]));
        }
        mx0 = fmaxf(mx0, __shfl_xor_sync(0xffffffffu, mx0, 1));
        mx0 = fmaxf(mx0, __shfl_xor_sync(0xffffffffu, mx0, 2));
        mx1 = fmaxf(mx1, __shfl_xor_sync(0xffffffffu, mx1, 1));
        mx1 = fmaxf(mx1, __shfl_xor_sync(0xffffffffu, mx1, 2));

        const float mn0 = fmaxf(m0, mx0);
        const float mn1 = fmaxf(m1, mx1);
        const float a0 = __expf(m0 - mn0);
        const float a1 = __expf(m1 - mn1);
        m0 = mn0; m1 = mn1;

        float s0 = 0.f, s1 = 0.f;
#pragma unroll
        for (int j = 0; j < 8; j++) {
            S[j][0] = __expf(S[j][0] - m0); s0 += S[j][0];
            S[j][1] = __expf(S[j][1] - m0); s0 += S[j][1];
            S[j][2] = __expf(S[j][2] - m1); s1 += S[j][2];
            S[j][3] = __expf(S[j][3] - m1); s1 += S[j][3];
        }
        s0 += __shfl_xor_sync(0xffffffffu, s0, 1);
        s0 += __shfl_xor_sync(0xffffffffu, s0, 2);
        s1 += __shfl_xor_sync(0xffffffffu, s1, 1);
        s1 += __shfl_xor_sync(0xffffffffu, s1, 2);
        l0 = l0 * a0 + s0;
        l1 = l1 * a1 + s1;

#pragma unroll
        for (int j = 0; j < 8; j++) {
            o[j][0] *= a0; o[j][1] *= a0;
            o[j][2] *= a1; o[j][3] *= a1;
        }

        // P accumulators -> A fragments, split bf16
        uint32_t pfh[4][4], pfl[4][4];
#pragma unroll
        for (int kk = 0; kk < 4; kk++) {
            bf16 h0, h1, lo0, lo1;
            split2(S[2 * kk][0], h0, lo0); split2(S[2 * kk][1], h1, lo1);
            pfh[kk][0] = pack_bf2(h0, h1); pfl[kk][0] = pack_bf2(lo0, lo1);
            split2(S[2 * kk][2], h0, lo0); split2(S[2 * kk][3], h1, lo1);
            pfh[kk][1] = pack_bf2(h0, h1); pfl[kk][1] = pack_bf2(lo0, lo1);
            split2(S[2 * kk + 1][0], h0, lo0); split2(S[2 * kk + 1][1], h1, lo1);
            pfh[kk][2] = pack_bf2(h0, h1); pfl[kk][2] = pack_bf2(lo0, lo1);
            split2(S[2 * kk + 1][2], h0, lo0); split2(S[2 * kk + 1][3], h1, lo1);
            pfh[kk][3] = pack_bf2(h0, h1); pfl[kk][3] = pack_bf2(lo0, lo1);
        }

        // O += P V
#pragma unroll
        for (int kk = 0; kk < 4; kk++) {
#pragma unroll
            for (int jd = 0; jd < 8; jd++) {
                uint32_t bh[2], bl[2];
                bh[0] = *reinterpret_cast<const uint32_t*>(&sVh[jd * 8 + gg][kk * 16 + 2 * tg]);
                bh[1] = *reinterpret_cast<const uint32_t*>(&sVh[jd * 8 + gg][kk * 16 + 2 * tg + 8]);
                bl[0] = *reinterpret_cast<const uint32_t*>(&sVl[jd * 8 + gg][kk * 16 + 2 * tg]);
                bl[1] = *reinterpret_cast<const uint32_t*>(&sVl[jd * 8 + gg][kk * 16 + 2 * tg + 8]);
                mma16816(o[jd], pfh[kk], bh);
                mma16816(o[jd], pfh[kk], bl);
                mma16816(o[jd], pfl[kk], bh);
            }
        }
        __syncthreads();
    }

    // epilogue: normalize, split-store ctx
    const float inv0 = 1.f / l0;
    const float inv1 = 1.f / l1;
    const size_t r_lo = (size_t)(b * SEQ) + mrow + gg;
    const size_t r_hi = r_lo + 8;
#pragma unroll
    for (int jd = 0; jd < 8; jd++) {
        const size_t c = hoff + jd * 8 + 2 * tg;
        float v0 = o[jd][0] * inv0, v1 = o[jd][1] * inv0;
        float v2 = o[jd][2] * inv1, v3 = o[jd][3] * inv1;
        bf16 h0, h1, h2, h3, lo0, lo1, lo2, lo3;
        split2(v0, h0, lo0); split2(v1, h1, lo1);
        split2(v2, h2, lo2); split2(v3, h3, lo3);
        *reinterpret_cast<__nv_bfloat162*>(ch + r_lo * HID + c) = __nv_bfloat162(h0, h1);
        *reinterpret_cast<__nv_bfloat162*>(ch + r_hi * HID + c) = __nv_bfloat162(h2, h3);
        *reinterpret_cast<__nv_bfloat162*>(cl + r_lo * HID + c) = __nv_bfloat162(lo0, lo1);
        *reinterpret_cast<__nv_bfloat162*>(cl + r_hi * HID + c) = __nv_bfloat162(lo2, lo3);
    }
}

// ---------------------------------------------------------------------------
// LayerNorm over HID=768, bf16 split outputs fused.
// ---------------------------------------------------------------------------
__global__ __launch_bounds__(256)
void layernorm_split(const float* __restrict__ x, const float* __restrict__ gam,
                     const float* __restrict__ bet, float* __restrict__ out,
                     bf16* __restrict__ oh, bf16* __restrict__ ol)
{
    const int row = blockIdx.x;
    const float* xr = x + (size_t)row * HID;
    const int tid = threadIdx.x;
    __shared__ float rs_[8], rq_[8];

    float v0 = xr[tid], v1 = xr[tid + 256], v2 = xr[tid + 512];
    float s  = v0 + v1 + v2;
    float sq = v0 * v0 + v1 * v1 + v2 * v2;
#pragma unroll
    for (int o = 16; o; o >>= 1) {
        s  += __shfl_xor_sync(0xffffffffu, s,  o);
        sq += __shfl_xor_sync(0xffffffffu, sq, o);
    }
    if ((tid & 31) == 0) { rs_[tid >> 5] = s; rq_[tid >> 5] = sq; }
    __syncthreads();
    float ts = 0.f, tq = 0.f;
#pragma unroll
    for (int i = 0; i < 8; i++) { ts += rs_[i]; tq += rq_[i]; }
    const float mean = ts * (1.f / HID);
    const float var  = tq * (1.f / HID) - mean * mean;
    const float rstd = rsqrtf(var + 1e-5f);

    float* o = out + (size_t)row * HID;
    float r0 = (v0 - mean) * rstd * gam[tid]       + bet[tid];
    float r1 = (v1 - mean) * rstd * gam[tid + 256] + bet[tid + 256];
    float r2 = (v2 - mean) * rstd * gam[tid + 512] + bet[tid + 512];
    o[tid] = r0; o[tid + 256] = r1; o[tid + 512] = r2;

    bf16 h, l;
    split2(r0, h, l); oh[(size_t)row * HID + tid]       = h; ol[(size_t)row * HID + tid]       = l;
    split2(r1, h, l); oh[(size_t)row * HID + tid + 256] = h; ol[(size_t)row * HID + tid + 256] = l;
    split2(r2, h, l); oh[(size_t)row * HID + tid + 512] = h; ol[(size_t)row * HID + tid + 512] = l;
}

// ---------------------------------------------------------------------------
// Launcher. Prologue is exactly 5 launches so the harness's fixed ncu window
// (-s 5 -c 1) captures the fused QKV tc_gemm (launch index 5).
// ---------------------------------------------------------------------------
extern "C" void kernel_launch(void* const* d_in, const int* in_sizes, int n_in,
                              void* d_out, int out_size)
{
    (void)in_sizes; (void)n_in; (void)out_size;
    const float* hs    = (const float*)d_in[0];
    const float* mask  = (const float*)d_in[1];
    const float* q_w   = (const float*)d_in[2];
    const float* q_b   = (const float*)d_in[3];
    const float* k_w   = (const float*)d_in[4];
    const float* k_b   = (const float*)d_in[5];
    const float* v_w   = (const float*)d_in[6];
    const float* v_b   = (const float*)d_in[7];
    const float* ao_w  = (const float*)d_in[8];
    const float* ao_b  = (const float*)d_in[9];
    const float* ln1_g = (const float*)d_in[10];
    const float* ln1_b = (const float*)d_in[11];
    const float* ff1_w = (const float*)d_in[12];
    const float* ff1_b = (const float*)d_in[13];
    const float* ff2_w = (const float*)d_in[14];
    const float* ff2_b = (const float*)d_in[15];
    const float* ln2_g = (const float*)d_in[16];
    const float* ln2_b = (const float*)d_in[17];
    float* out = (float*)d_out;

    float *x, *y, *attn, *y2, *qkvb;
    cudaGetSymbolAddress((void**)&x,    g_x);
    cudaGetSymbolAddress((void**)&y,    g_y);
    cudaGetSymbolAddress((void**)&attn, g_attn);
    cudaGetSymbolAddress((void**)&y2,   g_y2);
    cudaGetSymbolAddress((void**)&qkvb, g_qkvb);

    bf16 *xh,*xl,*qkvh,*qkvl,*vth,*vtl,*ch,*cl,*ah,*al,*fh,*fl;
    cudaGetSymbolAddress((void**)&xh,   g_xh);   cudaGetSymbolAddress((void**)&xl,   g_xl);
    cudaGetSymbolAddress((void**)&qkvh, g_qkvh); cudaGetSymbolAddress((void**)&qkvl, g_qkvl);
    cudaGetSymbolAddress((void**)&vth,  g_vth);  cudaGetSymbolAddress((void**)&vtl,  g_vtl);
    cudaGetSymbolAddress((void**)&ch,   g_ch);   cudaGetSymbolAddress((void**)&cl,   g_cl);
    cudaGetSymbolAddress((void**)&ah,   g_ah);   cudaGetSymbolAddress((void**)&al,   g_al);
    cudaGetSymbolAddress((void**)&fh,   g_fh);   cudaGetSymbolAddress((void**)&fl,   g_fl);

    bf16 *qkvwh,*qkvwl,*awh,*awl,*f1h,*f1l,*f2h,*f2l;
    cudaGetSymbolAddress((void**)&qkvwh, g_qkvwh); cudaGetSymbolAddress((void**)&qkvwl, g_qkvwl);
    cudaGetSymbolAddress((void**)&awh,   g_awh);   cudaGetSymbolAddress((void**)&awl,   g_awl);
    cudaGetSymbolAddress((void**)&f1h,   g_f1h);   cudaGetSymbolAddress((void**)&f1l,   g_f1l);
    cudaGetSymbolAddress((void**)&f2h,   g_f2h);   cudaGetSymbolAddress((void**)&f2l,   g_f2l);

    const int nHH = HID * HID, nHF = HID * FFDIM;
    // prologue: exactly 5 launches
    split_wT3<<<(nHH + 255) / 256, 256>>>(q_w, k_w, v_w, q_b, k_b, v_b,
                                          qkvwh, qkvwl, qkvb);          // 0
    split_wT<<<(nHH + 255) / 256, 256>>>(ao_w, awh, awl, HID, HID);     // 1
    split_wT<<<(nHF + 255) / 256, 256>>>(ff1_w, f1h, f1l, HID, FFDIM);  // 2
    split_wT<<<(nHF + 255) / 256, 256>>>(ff2_w, f2h, f2l, FFDIM, HID);  // 3
    const int nACT = MTOK * HID;
    split_act<<<(nACT / 4 + 255) / 256, 256>>>(hs, xh, xl, nACT);       // 4

    const dim3 gQKV(QKVD / 128, MTOK / 128);   // (18, 32)
    const dim3 gH  (HID   / 128, MTOK / 128);
    const dim3 gFF (FFDIM / 128, MTOK / 128);
    const dim3 gFA (SEQ / FBM, NBH);
    const dim3 gVT (SEQ / 32, HID / 32, BATCH);

    for (int l = 0; l < L_LAYERS; l++) {
        const float* xin = (l == 0) ? hs : x;

        tc_gemm<0, false, true><<<gQKV, 256>>>(xh, xl, qkvwh, qkvwl, qkvb, nullptr,
                                               nullptr, qkvh, qkvl, QKVD, HID);
        trans_v<<<gVT, dim3(32, 8)>>>(qkvh, qkvl, vth, vtl);

        flash_attn<<<gFA, 256>>>(qkvh, qkvl, vth, vtl, mask, ch, cl);

        tc_gemm<0, true, false><<<gH, 256>>>(ch, cl, awh, awl, ao_b, xin,
                                             y, nullptr, nullptr, HID, HID);
        layernorm_split<<<MTOK, 256>>>(y, ln1_g, ln1_b, attn, ah, al);

        tc_gemm<1, false, true><<<gFF, 256>>>(ah, al, f1h, f1l, ff1_b, nullptr,
                                              nullptr, fh, fl, FFDIM, HID);
        tc_gemm<0, true, false><<<gH, 256>>>(fh, fl, f2h, f2l, ff2_b, attn,
                                             y2, nullptr, nullptr, HID, FFDIM);

        float* xo = (l == L_LAYERS - 1) ? out : x;
        layernorm_split<<<MTOK, 256>>>(y2, ln2_g, ln2_b, xo, xh, xl);
    }
}

// round 15
// speedup vs baseline: 1.7717x; 1.3402x over previous
#include <cuda_runtime.h>
#include <cuda_bf16.h>
#include <math.h>
#include <stdint.h>

#define L_LAYERS 6
#define BATCH    4
#define SEQ      1024
#define HID      768
#define NHEAD    12
#define HDIM     64
#define FFDIM    3072
#define MTOK     (BATCH*SEQ)      // 4096 tokens
#define NBH      (BATCH*NHEAD)    // 48
#define FBM      128              // flash: query rows per CTA
#define FBN      64               // flash: keys per iteration
#define QKVD     2304             // fused QKV output width

typedef __nv_bfloat16 bf16;

// ---------------------------------------------------------------------------
// Scratch (device globals)
// ---------------------------------------------------------------------------
__device__ float g_x   [MTOK*HID];
__device__ float g_y   [MTOK*HID];
__device__ float g_attn[MTOK*HID];
__device__ float g_y2  [MTOK*HID];

__device__ bf16 g_xh[MTOK*HID],   g_xl[MTOK*HID];
__device__ bf16 g_qkvh[MTOK*QKVD],g_qkvl[MTOK*QKVD]; // fused QKV split
__device__ bf16 g_vth[MTOK*HID],  g_vtl[MTOK*HID];   // V^T per batch [HID][SEQ]
__device__ bf16 g_ch[MTOK*HID],   g_cl[MTOK*HID];    // ctx split
__device__ bf16 g_ah[MTOK*HID],   g_al[MTOK*HID];    // LN1 split
__device__ bf16 g_fh[MTOK*FFDIM], g_fl[MTOK*FFDIM];  // FF hidden split

// weights split, transposed [N,K]
__device__ bf16  g_qkvwh[QKVD*HID], g_qkvwl[QKVD*HID];
__device__ float g_qkvb[QKVD];
__device__ bf16  g_awh[HID*HID],   g_awl[HID*HID];
__device__ bf16  g_f1h[HID*FFDIM], g_f1l[HID*FFDIM];
__device__ bf16  g_f2h[FFDIM*HID], g_f2l[FFDIM*HID];

__device__ __forceinline__ void split2(float v, bf16& h, bf16& l)
{
    h = __float2bfloat16_rn(v);
    l = __float2bfloat16_rn(v - __bfloat162float(h));
}

__device__ __forceinline__ uint32_t pack_bf2(bf16 a, bf16 b)
{
    __nv_bfloat162 t(a, b);
    return *reinterpret_cast<uint32_t*>(&t);
}

// ---------------------------------------------------------------------------
// Split helpers
// ---------------------------------------------------------------------------
__global__ __launch_bounds__(256)
void split_act(const float* __restrict__ x, bf16* __restrict__ h,
               bf16* __restrict__ l, int n)
{
    int i = (blockIdx.x * 256 + threadIdx.x) * 4;
    if (i >= n) return;
    float4 v = *reinterpret_cast<const float4*>(x + i);
    bf16 h0, h1, h2, h3, l0, l1, l2, l3;
    split2(v.x, h0, l0); split2(v.y, h1, l1);
    split2(v.z, h2, l2); split2(v.w, h3, l3);
    __nv_bfloat162* hp = reinterpret_cast<__nv_bfloat162*>(h + i);
    __nv_bfloat162* lp = reinterpret_cast<__nv_bfloat162*>(l + i);
    hp[0] = __nv_bfloat162(h0, h1); hp[1] = __nv_bfloat162(h2, h3);
    lp[0] = __nv_bfloat162(l0, l1); lp[1] = __nv_bfloat162(l2, l3);
}

// W[K,N] row-major -> split, transposed to [N,K]
__global__ __launch_bounds__(256)
void split_wT(const float* __restrict__ W, bf16* __restrict__ hT,
              bf16* __restrict__ lT, int K, int N)
{
    int idx = blockIdx.x * 256 + threadIdx.x;
    if (idx >= K * N) return;
    int k = idx / N, n = idx - k * N;
    bf16 h, l;
    split2(W[idx], h, l);
    hT[(size_t)n * K + k] = h;
    lT[(size_t)n * K + k] = l;
}

// q/k/v weights [768,768] -> combined transposed [2304][768] + combined bias
__global__ __launch_bounds__(256)
void split_wT3(const float* __restrict__ Wq, const float* __restrict__ Wk,
               const float* __restrict__ Wv,
               const float* __restrict__ bq, const float* __restrict__ bk,
               const float* __restrict__ bv,
               bf16* __restrict__ hT, bf16* __restrict__ lT,
               float* __restrict__ bias)
{
    int idx = blockIdx.x * 256 + threadIdx.x;
    if (idx < QKVD) {
        bias[idx] = (idx < HID) ? bq[idx]
                  : (idx < 2 * HID) ? bk[idx - HID] : bv[idx - 2 * HID];
    }
    if (idx >= HID * HID) return;
    int k = idx / HID, n = idx - k * HID;
    bf16 h, l;
    split2(Wq[idx], h, l);
    hT[(size_t)n * HID + k] = h;               lT[(size_t)n * HID + k] = l;
    split2(Wk[idx], h, l);
    hT[(size_t)(n + HID) * HID + k] = h;       lT[(size_t)(n + HID) * HID + k] = l;
    split2(Wv[idx], h, l);
    hT[(size_t)(n + 2 * HID) * HID + k] = h;   lT[(size_t)(n + 2 * HID) * HID + k] = l;
}

// transpose split V from qkv buffer (cols [1536,2304)) -> [B][HID][SEQ]
__global__ __launch_bounds__(256)
void trans_v(const bf16* __restrict__ qkvh, const bf16* __restrict__ qkvl,
             bf16* __restrict__ th, bf16* __restrict__ tl)
{
    __shared__ bf16 t0[32][33];
    __shared__ bf16 t1[32][33];
    const int b  = blockIdx.z;
    const int s0 = blockIdx.x * 32;
    const int d0 = blockIdx.y * 32;
    const int x  = threadIdx.x;     // 0..31
    const int y  = threadIdx.y;     // 0..7
#pragma unroll
    for (int i = 0; i < 32; i += 8) {
        size_t g = ((size_t)b * SEQ + s0 + y + i) * QKVD + 2 * HID + d0 + x;
        t0[y + i][x] = qkvh[g];
        t1[y + i][x] = qkvl[g];
    }
    __syncthreads();
#pragma unroll
    for (int i = 0; i < 32; i += 8) {
        size_t o = ((size_t)b * HID + d0 + y + i) * SEQ + s0 + x;
        th[o] = t0[x][y + i];
        tl[o] = t1[x][y + i];
    }
}

// ---------------------------------------------------------------------------
// mma.sync m16n8k16 bf16 -> fp32  and ldmatrix helper
// ---------------------------------------------------------------------------
__device__ __forceinline__ void mma16816(float* c, const uint32_t* a, const uint32_t* b)
{
    asm("mma.sync.aligned.m16n8k16.row.col.f32.bf16.bf16.f32 "
        "{%0,%1,%2,%3}, {%4,%5,%6,%7}, {%8,%9}, {%0,%1,%2,%3};"
        : "+f"(c[0]), "+f"(c[1]), "+f"(c[2]), "+f"(c[3])
        : "r"(a[0]), "r"(a[1]), "r"(a[2]), "r"(a[3]), "r"(b[0]), "r"(b[1]));
}

__device__ __forceinline__ void ldm_x4(uint32_t* r, const void* smem_ptr)
{
    uint32_t addr = (uint32_t)__cvta_generic_to_shared(smem_ptr);
    asm volatile("ldmatrix.sync.aligned.m8n8.x4.shared.b16 {%0,%1,%2,%3}, [%4];"
                 : "=r"(r[0]), "=r"(r[1]), "=r"(r[2]), "=r"(r[3]) : "r"(addr));
}

// ---------------------------------------------------------------------------
// Dense tensor-core GEMM (3-term split): C = A@W + bias (+res)(+GELU)
// A:[M,K] split pair, W:[N,K] split pair. BM=BN=128, BK=16, 8 warps (2x4).
// Fragment loads via ldmatrix.x4 (12 per k-step, replacing 48 LDS.32).
// With 48B row stride each 8-address ldmatrix phase covers all 32 banks
// exactly once (conflict-free); rows are 16B-aligned via __align__(16).
// SPLITOUT: write bf16 (h,l) pair instead of fp32.
// ---------------------------------------------------------------------------
template<int ACT, bool HASRES, bool SPLITOUT>
__global__ __launch_bounds__(256, 1)
void tc_gemm(const bf16* __restrict__ Ah, const bf16* __restrict__ Al,
             const bf16* __restrict__ WhT, const bf16* __restrict__ WlT,
             const float* __restrict__ bias, const float* __restrict__ res,
             float* __restrict__ C, bf16* __restrict__ Oh, bf16* __restrict__ Ol,
             int Ndim, int Kdim)
{
    __shared__ __align__(16) bf16 sAh[2][128][24];
    __shared__ __align__(16) bf16 sAl[2][128][24];
    __shared__ __align__(16) bf16 sBh[2][128][24];
    __shared__ __align__(16) bf16 sBl[2][128][24];

    const int tid  = threadIdx.x;
    const int row0 = blockIdx.y * 128;
    const int col0 = blockIdx.x * 128;
    const int lrow = tid >> 1;
    const int kofs = (tid & 1) * 8;

    const bf16* pAh = Ah  + (size_t)(row0 + lrow) * Kdim + kofs;
    const bf16* pAl = Al  + (size_t)(row0 + lrow) * Kdim + kofs;
    const bf16* pBh = WhT + (size_t)(col0 + lrow) * Kdim + kofs;
    const bf16* pBl = WlT + (size_t)(col0 + lrow) * Kdim + kofs;

    const int wid  = tid >> 5;
    const int m0   = (wid & 1) * 64;
    const int n0   = (wid >> 1) * 32;
    const int lane = tid & 31;
    const int gg   = lane >> 2;
    const int tg   = lane & 3;

    // ldmatrix address selectors
    const int a_row = (lane & 7) + ((lane >> 3) & 1) * 8;  // 0..15 within m-tile
    const int a_col = (lane >> 4) * 8;                      // 0 or 8
    const int b_row = (lane & 7) + ((lane >> 4) & 1) * 8;  // 0..15 within n-pair
    const int b_col = ((lane >> 3) & 1) * 8;                // 0 or 8

    float acc[4][4][4];
#pragma unroll
    for (int i = 0; i < 4; i++)
#pragma unroll
        for (int j = 0; j < 4; j++)
#pragma unroll
            for (int t = 0; t < 4; t++) acc[i][j][t] = 0.f;

    {
        uint4 a_h = *reinterpret_cast<const uint4*>(pAh);
        uint4 a_l = *reinterpret_cast<const uint4*>(pAl);
        uint4 b_h = *reinterpret_cast<const uint4*>(pBh);
        uint4 b_l = *reinterpret_cast<const uint4*>(pBl);
        *reinterpret_cast<uint4*>(&sAh[0][lrow][kofs]) = a_h;
        *reinterpret_cast<uint4*>(&sAl[0][lrow][kofs]) = a_l;
        *reinterpret_cast<uint4*>(&sBh[0][lrow][kofs]) = b_h;
        *reinterpret_cast<uint4*>(&sBl[0][lrow][kofs]) = b_l;
    }
    __syncthreads();

    int s = 0;
    for (int k0 = 0; k0 < Kdim; k0 += 16) {
        const bool has_next = (k0 + 16 < Kdim);
        uint4 nAh, nAl, nBh, nBl;
        if (has_next) {
            nAh = *reinterpret_cast<const uint4*>(pAh + k0 + 16);
            nAl = *reinterpret_cast<const uint4*>(pAl + k0 + 16);
            nBh = *reinterpret_cast<const uint4*>(pBh + k0 + 16);
            nBl = *reinterpret_cast<const uint4*>(pBl + k0 + 16);
        }

        uint32_t afh[4][4], afl[4][4], bfh[4][2], bfl[4][2];
#pragma unroll
        for (int i = 0; i < 4; i++) {
            ldm_x4(afh[i], &sAh[s][m0 + i * 16 + a_row][a_col]);
            ldm_x4(afl[i], &sAl[s][m0 + i * 16 + a_row][a_col]);
        }
#pragma unroll
        for (int jp = 0; jp < 2; jp++) {
            uint32_t t4[4];
            ldm_x4(t4, &sBh[s][n0 + jp * 16 + b_row][b_col]);
            bfh[2 * jp][0] = t4[0]; bfh[2 * jp][1] = t4[1];
            bfh[2 * jp + 1][0] = t4[2]; bfh[2 * jp + 1][1] = t4[3];
            ldm_x4(t4, &sBl[s][n0 + jp * 16 + b_row][b_col]);
            bfl[2 * jp][0] = t4[0]; bfl[2 * jp][1] = t4[1];
            bfl[2 * jp + 1][0] = t4[2]; bfl[2 * jp + 1][1] = t4[3];
        }

#pragma unroll
        for (int i = 0; i < 4; i++)
#pragma unroll
            for (int j = 0; j < 4; j++) {
                mma16816(acc[i][j], afh[i], bfh[j]);
                mma16816(acc[i][j], afh[i], bfl[j]);
                mma16816(acc[i][j], afl[i], bfh[j]);
            }

        if (has_next) {
            const int ns = s ^ 1;
            *reinterpret_cast<uint4*>(&sAh[ns][lrow][kofs]) = nAh;
            *reinterpret_cast<uint4*>(&sAl[ns][lrow][kofs]) = nAl;
            *reinterpret_cast<uint4*>(&sBh[ns][lrow][kofs]) = nBh;
            *reinterpret_cast<uint4*>(&sBl[ns][lrow][kofs]) = nBl;
            __syncthreads();
        }
        s ^= 1;
    }

#pragma unroll
    for (int i = 0; i < 4; i++) {
        const int r_lo = row0 + m0 + i * 16 + gg;
        const int r_hi = r_lo + 8;
#pragma unroll
        for (int j = 0; j < 4; j++) {
            const int c = col0 + n0 + j * 8 + 2 * tg;
            float2 b2 = *reinterpret_cast<const float2*>(bias + c);
            float v0 = acc[i][j][0] + b2.x;
            float v1 = acc[i][j][1] + b2.y;
            float v2 = acc[i][j][2] + b2.x;
            float v3 = acc[i][j][3] + b2.y;
            if (HASRES) {
                float2 r0 = *reinterpret_cast<const float2*>(res + (size_t)r_lo * Ndim + c);
                float2 r1 = *reinterpret_cast<const float2*>(res + (size_t)r_hi * Ndim + c);
                v0 += r0.x; v1 += r0.y; v2 += r1.x; v3 += r1.y;
            }
            if (ACT == 1) {
                v0 = 0.5f * v0 * (1.f + erff(v0 * 0.7071067811865475f));
                v1 = 0.5f * v1 * (1.f + erff(v1 * 0.7071067811865475f));
                v2 = 0.5f * v2 * (1.f + erff(v2 * 0.7071067811865475f));
                v3 = 0.5f * v3 * (1.f + erff(v3 * 0.7071067811865475f));
            }
            if (SPLITOUT) {
                bf16 h0, h1, h2, h3, l0, l1, l2, l3;
                split2(v0, h0, l0); split2(v1, h1, l1);
                split2(v2, h2, l2); split2(v3, h3, l3);
                *reinterpret_cast<__nv_bfloat162*>(Oh + (size_t)r_lo * Ndim + c) = __nv_bfloat162(h0, h1);
                *reinterpret_cast<__nv_bfloat162*>(Oh + (size_t)r_hi * Ndim + c) = __nv_bfloat162(h2, h3);
                *reinterpret_cast<__nv_bfloat162*>(Ol + (size_t)r_lo * Ndim + c) = __nv_bfloat162(l0, l1);
                *reinterpret_cast<__nv_bfloat162*>(Ol + (size_t)r_hi * Ndim + c) = __nv_bfloat162(l2, l3);
            } else {
                *reinterpret_cast<float2*>(C + (size_t)r_lo * Ndim + c) = make_float2(v0, v1);
                *reinterpret_cast<float2*>(C + (size_t)r_hi * Ndim + c) = make_float2(v2, v3);
            }
        }
    }
}

// ---------------------------------------------------------------------------
// Fused flash attention (per (b,h)): ctx = softmax(QK^T/8 + mask) @ V
// Q,K live in the fused qkv buffer [B*S][QKVD] (Q at col h*64, K at 768+h*64);
// V^T split [B][HID][SEQ]; out split ctx [B,S,HID].
// ---------------------------------------------------------------------------
__global__ __launch_bounds__(256, 1)
void flash_attn(const bf16* __restrict__ qkvh, const bf16* __restrict__ qkvl,
                const bf16* __restrict__ vth, const bf16* __restrict__ vtl,
                const float* __restrict__ mask,
                bf16* __restrict__ ch, bf16* __restrict__ cl)
{
    __shared__ bf16 sKh[FBN][72], sKl[FBN][72];     // [key][d]
    __shared__ bf16 sVh[HDIM][72], sVl[HDIM][72];   // [d][key]
    __shared__ float sMask[SEQ];

    const int z = blockIdx.y;
    const int b = z / NHEAD, h = z % NHEAD;
    const int row0 = blockIdx.x * FBM;
    const int tid  = threadIdx.x;
    const int wid  = tid >> 5;
    const int lane = tid & 31;
    const int gg   = lane >> 2;
    const int tg   = lane & 3;
    const int mrow = row0 + wid * 16;   // warp's first query row
    const size_t hoff = (size_t)h * HDIM;

    for (int i = tid; i < SEQ; i += 256)
        sMask[i] = mask[(size_t)b * SEQ + i];

    // Q fragments (4 k-steps), loaded directly from gmem
    uint32_t qfh[4][4], qfl[4][4];
#pragma unroll
    for (int kk = 0; kk < 4; kk++) {
        const size_t r0 = ((size_t)(b * SEQ + mrow + gg))     * QKVD + hoff + kk * 16 + 2 * tg;
        const size_t r1 = ((size_t)(b * SEQ + mrow + 8 + gg)) * QKVD + hoff + kk * 16 + 2 * tg;
        qfh[kk][0] = *reinterpret_cast<const uint32_t*>(qkvh + r0);
        qfh[kk][1] = *reinterpret_cast<const uint32_t*>(qkvh + r1);
        qfh[kk][2] = *reinterpret_cast<const uint32_t*>(qkvh + r0 + 8);
        qfh[kk][3] = *reinterpret_cast<const uint32_t*>(qkvh + r1 + 8);
        qfl[kk][0] = *reinterpret_cast<const uint32_t*>(qkvl + r0);
        qfl[kk][1] = *reinterpret_cast<const uint32_t*>(qkvl + r1);
        qfl[kk][2] = *reinterpret_cast<const uint32_t*>(qkvl + r0 + 8);
        qfl[kk][3] = *reinterpret_cast<const uint32_t*>(qkvl + r1 + 8);
    }

    float o[8][4];
#pragma unroll
    for (int j = 0; j < 8; j++)
#pragma unroll
        for (int t = 0; t < 4; t++) o[j][t] = 0.f;
    float m0 = -1e30f, m1 = -1e30f, l0 = 0.f, l1 = 0.f;

    const int lrow = tid >> 2;        // 0..63
    const int lc   = (tid & 3) * 16;  // 0,16,32,48

    for (int k0 = 0; k0 < SEQ; k0 += FBN) {
        // stage K block (from qkv cols 768+h*64) and V^T block
        {
            const size_t gk = ((size_t)(b * SEQ + k0 + lrow)) * QKVD + HID + hoff + lc;
            *reinterpret_cast<uint4*>(&sKh[lrow][lc])     = *reinterpret_cast<const uint4*>(qkvh + gk);
            *reinterpret_cast<uint4*>(&sKh[lrow][lc + 8]) = *reinterpret_cast<const uint4*>(qkvh + gk + 8);
            *reinterpret_cast<uint4*>(&sKl[lrow][lc])     = *reinterpret_cast<const uint4*>(qkvl + gk);
            *reinterpret_cast<uint4*>(&sKl[lrow][lc + 8]) = *reinterpret_cast<const uint4*>(qkvl + gk + 8);
            const size_t gv = ((size_t)b * HID + hoff + lrow) * SEQ + k0 + lc;
            *reinterpret_cast<uint4*>(&sVh[lrow][lc])     = *reinterpret_cast<const uint4*>(vth + gv);
            *reinterpret_cast<uint4*>(&sVh[lrow][lc + 8]) = *reinterpret_cast<const uint4*>(vth + gv + 8);
            *reinterpret_cast<uint4*>(&sVl[lrow][lc])     = *reinterpret_cast<const uint4*>(vtl + gv);
            *reinterpret_cast<uint4*>(&sVl[lrow][lc + 8]) = *reinterpret_cast<const uint4*>(vtl + gv + 8);
        }
        __syncthreads();

        // S = Q K^T
        float S[8][4];
#pragma unroll
        for (int j = 0; j < 8; j++)
#pragma unroll
            for (int t = 0; t < 4; t++) S[j][t] = 0.f;

#pragma unroll
        for (int kk = 0; kk < 4; kk++) {
#pragma unroll
            for (int j = 0; j < 8; j++) {
                uint32_t bh[2], bl[2];
                bh[0] = *reinterpret_cast<const uint32_t*>(&sKh[j * 8 + gg][kk * 16 + 2 * tg]);
                bh[1] = *reinterpret_cast<const uint32_t*>(&sKh[j * 8 + gg][kk * 16 + 2 * tg + 8]);
                bl[0] = *reinterpret_cast<const uint32_t*>(&sKl[j * 8 + gg][kk * 16 + 2 * tg]);
                bl[1] = *reinterpret_cast<const uint32_t*>(&sKl[j * 8 + gg][kk * 16 + 2 * tg + 8]);
                mma16816(S[j], qfh[kk], bh);
                mma16816(S[j], qfh[kk], bl);
                mma16816(S[j], qfl[kk], bh);
            }
        }

        // scale + additive mask
#pragma unroll
        for (int j = 0; j < 8; j++) {
            const float mk0 = sMask[k0 + j * 8 + 2 * tg];
            const float mk1 = sMask[k0 + j * 8 + 2 * tg + 1];
            S[j][0] = S[j][0] * 0.125f + mk0;
            S[j][1] = S[j][1] * 0.125f + mk1;
            S[j][2] = S[j][2] * 0.125f + mk0;
            S[j][3] = S[j][3] * 0.125f + mk1;
        }

        // online softmax
        float mx0 = -1e30f, mx1 = -1e30f;
#pragma unroll
        for (int j = 0; j < 8; j++) {
            mx0 = fmaxf(mx0, fmaxf(S[j][0], S[j][1]));
            mx1 = fmaxf(mx1, fmaxf(S[j][2], S[j][3]));
        }
        mx0 = fmaxf(mx0, __shfl_xor_sync(0xffffffffu, mx0, 1));
        mx0 = fmaxf(mx0, __shfl_xor_sync(0xffffffffu, mx0, 2));
        mx1 = fmaxf(mx1, __shfl_xor_sync(0xffffffffu, mx1, 1));
        mx1 = fmaxf(mx1, __shfl_xor_sync(0xffffffffu, mx1, 2));

        const float mn0 = fmaxf(m0, mx0);
        const float mn1 = fmaxf(m1, mx1);
        const float a0 = __expf(m0 - mn0);
        const float a1 = __expf(m1 - mn1);
        m0 = mn0; m1 = mn1;

        float s0 = 0.f, s1 = 0.f;
#pragma unroll
        for (int j = 0; j < 8; j++) {
            S[j][0] = __expf(S[j][0] - m0); s0 += S[j][0];
            S[j][1] = __expf(S[j][1] - m0); s0 += S[j][1];
            S[j][2] = __expf(S[j][2] - m1); s1 += S[j][2];
            S[j][3] = __expf(S[j][3] - m1); s1 += S[j][3];
        }
        s0 += __shfl_xor_sync(0xffffffffu, s0, 1);
        s0 += __shfl_xor_sync(0xffffffffu, s0, 2);
        s1 += __shfl_xor_sync(0xffffffffu, s1, 1);
        s1 += __shfl_xor_sync(0xffffffffu, s1, 2);
        l0 = l0 * a0 + s0;
        l1 = l1 * a1 + s1;

#pragma unroll
        for (int j = 0; j < 8; j++) {
            o[j][0] *= a0; o[j][1] *= a0;
            o[j][2] *= a1; o[j][3] *= a1;
        }

        // P accumulators -> A fragments, split bf16
        uint32_t pfh[4][4], pfl[4][4];
#pragma unroll
        for (int kk = 0; kk < 4; kk++) {
            bf16 h0, h1, lo0, lo1;
            split2(S[2 * kk][0], h0, lo0); split2(S[2 * kk][1], h1, lo1);
            pfh[kk][0] = pack_bf2(h0, h1); pfl[kk][0] = pack_bf2(lo0, lo1);
            split2(S[2 * kk][2], h0, lo0); split2(S[2 * kk][3], h1, lo1);
            pfh[kk][1] = pack_bf2(h0, h1); pfl[kk][1] = pack_bf2(lo0, lo1);
            split2(S[2 * kk + 1][0], h0, lo0); split2(S[2 * kk + 1][1], h1, lo1);
            pfh[kk][2] = pack_bf2(h0, h1); pfl[kk][2] = pack_bf2(lo0, lo1);
            split2(S[2 * kk + 1][2], h0, lo0); split2(S[2 * kk + 1][3], h1, lo1);
            pfh[kk][3] = pack_bf2(h0, h1); pfl[kk][3] = pack_bf2(lo0, lo1);
        }

        // O += P V
#pragma unroll
        for (int kk = 0; kk < 4; kk++) {
#pragma unroll
            for (int jd = 0; jd < 8; jd++) {
                uint32_t bh[2], bl[2];
                bh[0] = *reinterpret_cast<const uint32_t*>(&sVh[jd * 8 + gg][kk * 16 + 2 * tg]);
                bh[1] = *reinterpret_cast<const uint32_t*>(&sVh[jd * 8 + gg][kk * 16 + 2 * tg + 8]);
                bl[0] = *reinterpret_cast<const uint32_t*>(&sVl[jd * 8 + gg][kk * 16 + 2 * tg]);
                bl[1] = *reinterpret_cast<const uint32_t*>(&sVl[jd * 8 + gg][kk * 16 + 2 * tg + 8]);
                mma16816(o[jd], pfh[kk], bh);
                mma16816(o[jd], pfh[kk], bl);
                mma16816(o[jd], pfl[kk], bh);
            }
        }
        __syncthreads();
    }

    // epilogue: normalize, split-store ctx
    const float inv0 = 1.f / l0;
    const float inv1 = 1.f / l1;
    const size_t r_lo = (size_t)(b * SEQ) + mrow + gg;
    const size_t r_hi = r_lo + 8;
#pragma unroll
    for (int jd = 0; jd < 8; jd++) {
        const size_t c = hoff + jd * 8 + 2 * tg;
        float v0 = o[jd][0] * inv0, v1 = o[jd][1] * inv0;
        float v2 = o[jd][2] * inv1, v3 = o[jd][3] * inv1;
        bf16 h0, h1, h2, h3, lo0, lo1, lo2, lo3;
        split2(v0, h0, lo0); split2(v1, h1, lo1);
        split2(v2, h2, lo2); split2(v3, h3, lo3);
        *reinterpret_cast<__nv_bfloat162*>(ch + r_lo * HID + c) = __nv_bfloat162(h0, h1);
        *reinterpret_cast<__nv_bfloat162*>(ch + r_hi * HID + c) = __nv_bfloat162(h2, h3);
        *reinterpret_cast<__nv_bfloat162*>(cl + r_lo * HID + c) = __nv_bfloat162(lo0, lo1);
        *reinterpret_cast<__nv_bfloat162*>(cl + r_hi * HID + c) = __nv_bfloat162(lo2, lo3);
    }
}

// ---------------------------------------------------------------------------
// LayerNorm over HID=768, bf16 split outputs fused.
// ---------------------------------------------------------------------------
__global__ __launch_bounds__(256)
void layernorm_split(const float* __restrict__ x, const float* __restrict__ gam,
                     const float* __restrict__ bet, float* __restrict__ out,
                     bf16* __restrict__ oh, bf16* __restrict__ ol)
{
    const int row = blockIdx.x;
    const float* xr = x + (size_t)row * HID;
    const int tid = threadIdx.x;
    __shared__ float rs_[8], rq_[8];

    float v0 = xr[tid], v1 = xr[tid + 256], v2 = xr[tid + 512];
    float s  = v0 + v1 + v2;
    float sq = v0 * v0 + v1 * v1 + v2 * v2;
#pragma unroll
    for (int o = 16; o; o >>= 1) {
        s  += __shfl_xor_sync(0xffffffffu, s,  o);
        sq += __shfl_xor_sync(0xffffffffu, sq, o);
    }
    if ((tid & 31) == 0) { rs_[tid >> 5] = s; rq_[tid >> 5] = sq; }
    __syncthreads();
    float ts = 0.f, tq = 0.f;
#pragma unroll
    for (int i = 0; i < 8; i++) { ts += rs_[i]; tq += rq_[i]; }
    const float mean = ts * (1.f / HID);
    const float var  = tq * (1.f / HID) - mean * mean;
    const float rstd = rsqrtf(var + 1e-5f);

    float* o = out + (size_t)row * HID;
    float r0 = (v0 - mean) * rstd * gam[tid]       + bet[tid];
    float r1 = (v1 - mean) * rstd * gam[tid + 256] + bet[tid + 256];
    float r2 = (v2 - mean) * rstd * gam[tid + 512] + bet[tid + 512];
    o[tid] = r0; o[tid + 256] = r1; o[tid + 512] = r2;

    bf16 h, l;
    split2(r0, h, l); oh[(size_t)row * HID + tid]       = h; ol[(size_t)row * HID + tid]       = l;
    split2(r1, h, l); oh[(size_t)row * HID + tid + 256] = h; ol[(size_t)row * HID + tid + 256] = l;
    split2(r2, h, l); oh[(size_t)row * HID + tid + 512] = h; ol[(size_t)row * HID + tid + 512] = l;
}

// ---------------------------------------------------------------------------
// Launcher
// ---------------------------------------------------------------------------
extern "C" void kernel_launch(void* const* d_in, const int* in_sizes, int n_in,
                              void* d_out, int out_size)
{
    (void)in_sizes; (void)n_in; (void)out_size;
    const float* hs    = (const float*)d_in[0];
    const float* mask  = (const float*)d_in[1];
    const float* q_w   = (const float*)d_in[2];
    const float* q_b   = (const float*)d_in[3];
    const float* k_w   = (const float*)d_in[4];
    const float* k_b   = (const float*)d_in[5];
    const float* v_w   = (const float*)d_in[6];
    const float* v_b   = (const float*)d_in[7];
    const float* ao_w  = (const float*)d_in[8];
    const float* ao_b  = (const float*)d_in[9];
    const float* ln1_g = (const float*)d_in[10];
    const float* ln1_b = (const float*)d_in[11];
    const float* ff1_w = (const float*)d_in[12];
    const float* ff1_b = (const float*)d_in[13];
    const float* ff2_w = (const float*)d_in[14];
    const float* ff2_b = (const float*)d_in[15];
    const float* ln2_g = (const float*)d_in[16];
    const float* ln2_b = (const float*)d_in[17];
    float* out = (float*)d_out;

    float *x, *y, *attn, *y2, *qkvb;
    cudaGetSymbolAddress((void**)&x,    g_x);
    cudaGetSymbolAddress((void**)&y,    g_y);
    cudaGetSymbolAddress((void**)&attn, g_attn);
    cudaGetSymbolAddress((void**)&y2,   g_y2);
    cudaGetSymbolAddress((void**)&qkvb, g_qkvb);

    bf16 *xh,*xl,*qkvh,*qkvl,*vth,*vtl,*ch,*cl,*ah,*al,*fh,*fl;
    cudaGetSymbolAddress((void**)&xh,   g_xh);   cudaGetSymbolAddress((void**)&xl,   g_xl);
    cudaGetSymbolAddress((void**)&qkvh, g_qkvh); cudaGetSymbolAddress((void**)&qkvl, g_qkvl);
    cudaGetSymbolAddress((void**)&vth,  g_vth);  cudaGetSymbolAddress((void**)&vtl,  g_vtl);
    cudaGetSymbolAddress((void**)&ch,   g_ch);   cudaGetSymbolAddress((void**)&cl,   g_cl);
    cudaGetSymbolAddress((void**)&ah,   g_ah);   cudaGetSymbolAddress((void**)&al,   g_al);
    cudaGetSymbolAddress((void**)&fh,   g_fh);   cudaGetSymbolAddress((void**)&fl,   g_fl);

    bf16 *qkvwh,*qkvwl,*awh,*awl,*f1h,*f1l,*f2h,*f2l;
    cudaGetSymbolAddress((void**)&qkvwh, g_qkvwh); cudaGetSymbolAddress((void**)&qkvwl, g_qkvwl);
    cudaGetSymbolAddress((void**)&awh,   g_awh);   cudaGetSymbolAddress((void**)&awl,   g_awl);
    cudaGetSymbolAddress((void**)&f1h,   g_f1h);   cudaGetSymbolAddress((void**)&f1l,   g_f1l);
    cudaGetSymbolAddress((void**)&f2h,   g_f2h);   cudaGetSymbolAddress((void**)&f2l,   g_f2l);

    const int nHH = HID * HID, nHF = HID * FFDIM;
    split_wT3<<<(nHH + 255) / 256, 256>>>(q_w, k_w, v_w, q_b, k_b, v_b,
                                          qkvwh, qkvwl, qkvb);
    split_wT<<<(nHH + 255) / 256, 256>>>(ao_w, awh, awl, HID, HID);
    split_wT<<<(nHF + 255) / 256, 256>>>(ff1_w, f1h, f1l, HID, FFDIM);
    split_wT<<<(nHF + 255) / 256, 256>>>(ff2_w, f2h, f2l, FFDIM, HID);
    const int nACT = MTOK * HID;
    split_act<<<(nACT / 4 + 255) / 256, 256>>>(hs, xh, xl, nACT);

    const dim3 gQKV(QKVD / 128, MTOK / 128);   // (18, 32)
    const dim3 gH  (HID   / 128, MTOK / 128);
    const dim3 gFF (FFDIM / 128, MTOK / 128);
    const dim3 gFA (SEQ / FBM, NBH);
    const dim3 gVT (SEQ / 32, HID / 32, BATCH);

    for (int l = 0; l < L_LAYERS; l++) {
        const float* xin = (l == 0) ? hs : x;

        tc_gemm<0, false, true><<<gQKV, 256>>>(xh, xl, qkvwh, qkvwl, qkvb, nullptr,
                                               nullptr, qkvh, qkvl, QKVD, HID);
        trans_v<<<gVT, dim3(32, 8)>>>(qkvh, qkvl, vth, vtl);

        flash_attn<<<gFA, 256>>>(qkvh, qkvl, vth, vtl, mask, ch, cl);

        tc_gemm<0, true, false><<<gH, 256>>>(ch, cl, awh, awl, ao_b, xin,
                                             y, nullptr, nullptr, HID, HID);
        layernorm_split<<<MTOK, 256>>>(y, ln1_g, ln1_b, attn, ah, al);

        tc_gemm<1, false, true><<<gFF, 256>>>(ah, al, f1h, f1l, ff1_b, nullptr,
                                              nullptr, fh, fl, FFDIM, HID);
        tc_gemm<0, true, false><<<gH, 256>>>(fh, fl, f2h, f2l, ff2_b, attn,
                                             y2, nullptr, nullptr, HID, FFDIM);

        float* xo = (l == L_LAYERS - 1) ? out : x;
        layernorm_split<<<MTOK, 256>>>(y2, ln2_g, ln2_b, xo, xh, xl);
    }
}